// round 9
// baseline (speedup 1.0000x reference)
#include <cuda_runtime.h>
#include <cuda_fp16.h>
#include <math.h>

#define BB 2
#define NN 2048
#define DD 128
#define HH 16
#define ALLD 2048
#define BN  4096

#define BQ 64          // q rows per attention block (4 warps x 16)
#define TK 64          // keys per tile
#define NT (NN / TK)

#define KS_STR 136     // halves per K row   (272B stride: LDSM conflict-free)
#define VT_STR 72      // halves per V^T row (144B stride: LDSM conflict-free)

// Scratch
__device__ __half g_xh [BN*DD];         // x as half
__device__ __half g_Wt [3*ALLD*DD];     // W{q,k,v}^T as half [n][k], SC folded into Wq
__device__ __half g_Wot[DD*ALLD];       // Wo^T as half [n][k]
__device__ __half g_Qh [BB*HH*NN*DD];   // [bh][n][d], pre-scaled
__device__ __half g_Kh [BB*HH*NN*DD];   // [bh][n][d]
__device__ __half g_Vh [BB*HH*NN*DD];   // [bh][n][d]
__device__ __half g_Vth[BB*HH*DD*NN];   // [bh][d][n]
__device__ __half g_Ch [BB*NN*ALLD];    // ctx as half [n][ALLD]

__device__ __forceinline__ unsigned h2pack(float x, float y) {
    __half2 h = __floats2half2_rn(x, y);
    return *(unsigned*)&h;
}

__device__ __forceinline__ void mma16(float* c,
                                      unsigned a0, unsigned a1, unsigned a2, unsigned a3,
                                      unsigned b0, unsigned b1) {
    asm volatile(
        "mma.sync.aligned.m16n8k16.row.col.f32.f16.f16.f32 "
        "{%0,%1,%2,%3}, {%4,%5,%6,%7}, {%8,%9}, {%0,%1,%2,%3};"
        : "+f"(c[0]), "+f"(c[1]), "+f"(c[2]), "+f"(c[3])
        : "r"(a0), "r"(a1), "r"(a2), "r"(a3), "r"(b0), "r"(b1));
}

__device__ __forceinline__ void ldsm4(unsigned& r0, unsigned& r1,
                                      unsigned& r2, unsigned& r3, unsigned addr) {
    asm volatile("ldmatrix.sync.aligned.m8n8.x4.shared.b16 {%0,%1,%2,%3}, [%4];"
        : "=r"(r0), "=r"(r1), "=r"(r2), "=r"(r3) : "r"(addr));
}

__device__ __forceinline__ void cp16(unsigned dst, const void* src) {
    asm volatile("cp.async.cg.shared.global [%0], [%1], 16;" :: "r"(dst), "l"(src));
}

#define SCQ 0.08838834764831845f   // 1/sqrt(128)

// ---------------------------------------------------------------------------
// Kernel 0: convert x and weights to half (weights transposed, SC folded).
// ---------------------------------------------------------------------------
#define N_XH  (BN*DD)
#define N_WT  (3*ALLD*DD)
#define N_WOT (DD*ALLD)
#define N_CVT (N_XH + N_WT + N_WOT)

__global__ __launch_bounds__(256)
void convert_kernel(const float* __restrict__ x,
                    const float* __restrict__ Wq,
                    const float* __restrict__ Wk,
                    const float* __restrict__ Wv,
                    const float* __restrict__ Wo)
{
    const int idx = blockIdx.x * 256 + threadIdx.x;
    if (idx < N_XH) {
        g_xh[idx] = __float2half_rn(x[idx]);
    } else if (idx < N_XH + N_WT) {
        const int i = idx - N_XH;
        const int r = i >> 7;
        const int k = i & 127;
        const int proj = r >> 11;
        const int c    = r & 2047;
        const float v = (proj == 0) ? Wq[k * ALLD + c] * SCQ
                      : (proj == 1) ? Wk[k * ALLD + c]
                                    : Wv[k * ALLD + c];
        g_Wt[i] = __float2half_rn(v);
    } else if (idx < N_CVT) {
        const int i = idx - N_XH - N_WT;
        const int n = i >> 11;
        const int k = i & 2047;
        g_Wot[i] = __float2half_rn(Wo[k * DD + n]);
    }
}

// ---------------------------------------------------------------------------
// Kernel 1: QKV projection as fp16 MMA GEMM (unchanged).
// ---------------------------------------------------------------------------
#define GQ_XS_STR 136
#define GQ_XS_BYTES (64 * GQ_XS_STR * 2)
#define GQ_WS_BYTES (128 * GQ_XS_STR * 2)

__global__ __launch_bounds__(128)
void gemm_qkv_kernel(const float* __restrict__ bq,
                     const float* __restrict__ bk,
                     const float* __restrict__ bv)
{
    extern __shared__ char sm[];
    __half* xs = (__half*)sm;
    __half* ws = (__half*)(sm + GQ_XS_BYTES);

    const int r0 = blockIdx.x * 64;
    const int n0 = blockIdx.y * 128;
    const int proj = n0 >> 11;
    const int h    = (n0 >> 7) & 15;

    const int t    = threadIdx.x;
    const int warp = t >> 5;
    const int lane = t & 31;
    const int g    = lane >> 2;
    const int tg   = lane & 3;
    const int m0   = warp * 16;

    const unsigned smu = (unsigned)__cvta_generic_to_shared(sm);

    #pragma unroll
    for (int p = 0; p < 8; p++) {
        const int c   = t + p * 128;
        const int row = c >> 4;
        const int cd  = (c & 15) * 8;
        cp16(smu + (row * GQ_XS_STR + cd) * 2, g_xh + (size_t)(r0 + row) * DD + cd);
    }
    #pragma unroll
    for (int p = 0; p < 16; p++) {
        const int c   = t + p * 128;
        const int row = c >> 4;
        const int cd  = (c & 15) * 8;
        cp16(smu + GQ_XS_BYTES + (row * GQ_XS_STR + cd) * 2,
             g_Wt + (size_t)(n0 + row) * DD + cd);
    }
    asm volatile("cp.async.commit_group;" ::: "memory");
    asm volatile("cp.async.wait_group 0;" ::: "memory");
    __syncthreads();

    float acc[16][4];
    #pragma unroll
    for (int j = 0; j < 16; j++) { acc[j][0]=0.f; acc[j][1]=0.f; acc[j][2]=0.f; acc[j][3]=0.f; }

    #pragma unroll
    for (int s = 0; s < 8; s++) {
        const int kc = 16 * s + 2 * tg;
        const unsigned a0 = *(const unsigned*)&xs[(m0 + g)     * GQ_XS_STR + kc];
        const unsigned a1 = *(const unsigned*)&xs[(m0 + g + 8) * GQ_XS_STR + kc];
        const unsigned a2 = *(const unsigned*)&xs[(m0 + g)     * GQ_XS_STR + kc + 8];
        const unsigned a3 = *(const unsigned*)&xs[(m0 + g + 8) * GQ_XS_STR + kc + 8];
        #pragma unroll
        for (int j = 0; j < 16; j++) {
            const unsigned b0 = *(const unsigned*)&ws[(8 * j + g) * GQ_XS_STR + kc];
            const unsigned b1 = *(const unsigned*)&ws[(8 * j + g) * GQ_XS_STR + kc + 8];
            mma16(acc[j], a0, a1, a2, a3, b0, b1);
        }
    }

    const float* bias = (proj == 0) ? bq : (proj == 1) ? bk : bv;
    const float  bscl = (proj == 0) ? SCQ : 1.0f;
    __half* dst = (proj == 0) ? g_Qh : (proj == 1) ? g_Kh : g_Vh;
    const int bcol = n0 & 2047;

    const int row0 = r0 + m0 + g;
    const int row1 = row0 + 8;
    const int b0i  = row0 >> 11, nn0 = row0 & 2047;
    const int b1i  = row1 >> 11, nn1 = row1 & 2047;
    __half* d0 = dst + (((size_t)(b0i * HH + h)) * NN + nn0) * DD;
    __half* d1 = dst + (((size_t)(b1i * HH + h)) * NN + nn1) * DD;

    #pragma unroll
    for (int j = 0; j < 16; j++) {
        const int ci = 8 * j + 2 * tg;
        const float bb0 = bias[bcol + ci]     * bscl;
        const float bb1 = bias[bcol + ci + 1] * bscl;
        *(unsigned*)&d0[ci] = h2pack(acc[j][0] + bb0, acc[j][1] + bb1);
        *(unsigned*)&d1[ci] = h2pack(acc[j][2] + bb0, acc[j][3] + bb1);
    }
}

// ---------------------------------------------------------------------------
// Kernel 1b: V transpose (unchanged).
// ---------------------------------------------------------------------------
__global__ __launch_bounds__(256)
void transpose_v_kernel()
{
    __shared__ __half ts[64 * 136];

    const int bh  = blockIdx.x >> 5;
    const int nt  = blockIdx.x & 31;
    const int n0  = nt * 64;
    const int t   = threadIdx.x;

    const __half* src = g_Vh + ((size_t)bh * NN + n0) * DD;
    #pragma unroll
    for (int p = 0; p < 4; p++) {
        const int c   = t + p * 256;
        const int row = c >> 4;
        const int cd  = (c & 15) * 8;
        *(uint4*)&ts[row * 136 + cd] = *(const uint4*)&src[row * DD + cd];
    }
    __syncthreads();

    const int d  = t >> 1;
    const int hn = (t & 1) * 32;
    __half* dst = g_Vth + ((size_t)bh * DD + d) * NN + n0 + hn;
    #pragma unroll
    for (int c = 0; c < 32; c += 2) {
        const int n = hn + c;
        *(unsigned*)&dst[c] = h2pack(__half2float(ts[n * 136 + d]),
                                     __half2float(ts[(n + 1) * 136 + d]));
    }
}

// ---------------------------------------------------------------------------
// Kernel 2: flash attention — B fragments now via ldmatrix.x4.
// ---------------------------------------------------------------------------
#define KS_BYTES (TK * KS_STR * 2)
#define VT_BYTES (DD * VT_STR * 2)
#define SM_KS(buf)  ((buf) * KS_BYTES)
#define SM_VT(buf)  (2 * KS_BYTES + (buf) * VT_BYTES)
#define SM_MK(buf)  (2 * KS_BYTES + 2 * VT_BYTES + (buf) * 256)
#define ATT_SMEM    (2 * KS_BYTES + 2 * VT_BYTES + 512)

__global__ __launch_bounds__(128, 3)
void attn_fp16_kernel(const int* __restrict__ mask)
{
    extern __shared__ char sm[];

    const int bid = blockIdx.x;
    const int qt  = bid & 31;
    const int bh  = bid >> 5;
    const int h   = bh & 15;
    const int b   = bh >> 4;
    const int n0  = qt * BQ;

    const int t    = threadIdx.x;
    const int warp = t >> 5;
    const int lane = t & 31;
    const int g    = lane >> 2;
    const int tg   = lane & 3;
    const int m0   = warp * 16;

    // ldmatrix lane addressing: row-within-tile and tile index
    const int lrow  = lane & 7;
    const int ltile = (lane >> 3) & 3;

    const __half* Qh  = g_Qh  + (size_t)bh * NN * DD;
    const __half* Kh  = g_Kh  + (size_t)bh * NN * DD;
    const __half* Vth = g_Vth + (size_t)bh * DD * NN;
    const int*    mg  = mask + b * NN;

    const unsigned smu = (unsigned)__cvta_generic_to_shared(sm);

    auto stage = [&](int kt, int buf) {
        const int k0 = kt * TK;
        const unsigned ksu = smu + SM_KS(buf);
        const unsigned vtu = smu + SM_VT(buf);
        #pragma unroll
        for (int p = 0; p < 8; p++) {
            const int c   = t + p * 128;
            const int row = c >> 4;
            const int cd  = (c & 15) * 8;
            cp16(ksu + (row * KS_STR + cd) * 2, Kh + (size_t)(k0 + row) * DD + cd);
        }
        #pragma unroll
        for (int p = 0; p < 8; p++) {
            const int c   = t + p * 128;
            const int row = c >> 3;
            const int cd  = (c & 7) * 8;
            cp16(vtu + (row * VT_STR + cd) * 2, Vth + (size_t)row * NN + k0 + cd);
        }
        if (t < TK) ((int*)(sm + SM_MK(buf)))[t] = mg[k0 + t];
        asm volatile("cp.async.commit_group;" ::: "memory");
    };

    unsigned qa[8][4];
    {
        const __half* q0 = Qh + (size_t)(n0 + m0 + g)     * DD;
        const __half* q1 = Qh + (size_t)(n0 + m0 + g + 8) * DD;
        #pragma unroll
        for (int s = 0; s < 8; s++) {
            const int c = 16 * s + 2 * tg;
            qa[s][0] = *(const unsigned*)&q0[c];
            qa[s][1] = *(const unsigned*)&q1[c];
            qa[s][2] = *(const unsigned*)&q0[c + 8];
            qa[s][3] = *(const unsigned*)&q1[c + 8];
        }
    }

    stage(0, 0);

    float o[16][4];
    #pragma unroll
    for (int j = 0; j < 16; j++) { o[j][0]=0.f; o[j][1]=0.f; o[j][2]=0.f; o[j][3]=0.f; }
    float l0 = 0.f, l1 = 0.f;

    for (int kt = 0; kt < NT; kt++) {
        const int buf = kt & 1;
        asm volatile("cp.async.wait_group 0;" ::: "memory");
        __syncthreads();

        if (kt + 1 < NT) stage(kt + 1, buf ^ 1);

        const unsigned ksu = smu + SM_KS(buf);
        const unsigned vtu = smu + SM_VT(buf);
        const int*     mk  = (const int*)(sm + SM_MK(buf));

        // ---- S = Q @ K^T : per key-tile j, 4 LDSM.x4 feed 8 k-steps ----
        float sc[8][4];
        #pragma unroll
        for (int j = 0; j < 8; j++) { sc[j][0]=0.f; sc[j][1]=0.f; sc[j][2]=0.f; sc[j][3]=0.f; }

        #pragma unroll
        for (int j = 0; j < 8; j++) {
            unsigned bf[16];
            #pragma unroll
            for (int sp = 0; sp < 4; sp++) {
                const unsigned addr = ksu +
                    ((8 * j + lrow) * KS_STR + 32 * sp + 8 * ltile) * 2;
                ldsm4(bf[4*sp], bf[4*sp+1], bf[4*sp+2], bf[4*sp+3], addr);
            }
            #pragma unroll
            for (int s = 0; s < 8; s++)
                mma16(sc[j], qa[s][0], qa[s][1], qa[s][2], qa[s][3],
                      bf[2*s], bf[2*s+1]);
        }

        // ---- fixed-max softmax; pack P directly into PV A-fragments ----
        unsigned pa[4][4];
        #pragma unroll
        for (int j = 0; j < 8; j++) {
            const int ci = 8 * j + 2 * tg;
            const int2 mm = *(const int2*)&mk[ci];
            const float e0 = mm.x ? __expf(sc[j][0]) : 0.f;
            const float e1 = mm.y ? __expf(sc[j][1]) : 0.f;
            const float e2 = mm.x ? __expf(sc[j][2]) : 0.f;
            const float e3 = mm.y ? __expf(sc[j][3]) : 0.f;
            l0 += e0 + e1;
            l1 += e2 + e3;
            const unsigned h01 = h2pack(e0, e1);
            const unsigned h23 = h2pack(e2, e3);
            const int s2 = j >> 1;
            if ((j & 1) == 0) { pa[s2][0] = h01; pa[s2][1] = h23; }
            else              { pa[s2][2] = h01; pa[s2][3] = h23; }
        }

        // ---- O += P @ V : per d-tile j2, 2 LDSM.x4 feed 4 k-steps ----
        #pragma unroll
        for (int j2 = 0; j2 < 16; j2++) {
            unsigned bf[8];
            #pragma unroll
            for (int sp = 0; sp < 2; sp++) {
                const unsigned addr = vtu +
                    ((8 * j2 + lrow) * VT_STR + 32 * sp + 8 * ltile) * 2;
                ldsm4(bf[4*sp], bf[4*sp+1], bf[4*sp+2], bf[4*sp+3], addr);
            }
            #pragma unroll
            for (int s2 = 0; s2 < 4; s2++)
                mma16(o[j2], pa[s2][0], pa[s2][1], pa[s2][2], pa[s2][3],
                      bf[2*s2], bf[2*s2+1]);
        }
        __syncthreads();
    }

    l0 += __shfl_xor_sync(0xffffffffu, l0, 1);
    l0 += __shfl_xor_sync(0xffffffffu, l0, 2);
    l1 += __shfl_xor_sync(0xffffffffu, l1, 1);
    l1 += __shfl_xor_sync(0xffffffffu, l1, 2);

    const int   qm0  = mg[n0 + m0 + g];
    const int   qm1  = mg[n0 + m0 + g + 8];
    const float inv0 = qm0 ? 1.0f / l0 : 0.f;
    const float inv1 = qm1 ? 1.0f / l1 : 0.f;

    __half* ctx0 = g_Ch + ((size_t)(b * NN + n0 + m0 + g))     * ALLD + h * DD;
    __half* ctx1 = g_Ch + ((size_t)(b * NN + n0 + m0 + g + 8)) * ALLD + h * DD;
    #pragma unroll
    for (int j2 = 0; j2 < 16; j2++) {
        const int ci = 8 * j2 + 2 * tg;
        *(unsigned*)&ctx0[ci] = h2pack(o[j2][0] * inv0, o[j2][1] * inv0);
        *(unsigned*)&ctx1[ci] = h2pack(o[j2][2] * inv1, o[j2][3] * inv1);
    }
}

// ---------------------------------------------------------------------------
// Kernel 3: output projection as fp16 MMA GEMM (unchanged).
// ---------------------------------------------------------------------------
#define GO_AS_STR 72
#define GO_AS_BYTES (32 * GO_AS_STR * 2)
#define GO_WS_BYTES (128 * GO_AS_STR * 2)
#define GO_SM_A(buf) ((buf) * (GO_AS_BYTES + GO_WS_BYTES))
#define GO_SM_W(buf) (GO_SM_A(buf) + GO_AS_BYTES)
#define GO_SMEM (2 * (GO_AS_BYTES + GO_WS_BYTES))

__global__ __launch_bounds__(128)
void gemm_out_kernel(const float* __restrict__ bo, float* __restrict__ out)
{
    extern __shared__ char sm[];

    const int r0   = blockIdx.x * 32;
    const int t    = threadIdx.x;
    const int warp = t >> 5;
    const int lane = t & 31;
    const int g    = lane >> 2;
    const int tg   = lane & 3;

    const unsigned smu = (unsigned)__cvta_generic_to_shared(sm);

    auto stage = [&](int kt, int buf) {
        const int k0 = kt * 64;
        const unsigned au = smu + GO_SM_A(buf);
        const unsigned wu = smu + GO_SM_W(buf);
        #pragma unroll
        for (int p = 0; p < 2; p++) {
            const int c   = t + p * 128;
            const int row = c >> 3;
            const int cd  = (c & 7) * 8;
            cp16(au + (row * GO_AS_STR + cd) * 2, g_Ch + (size_t)(r0 + row) * ALLD + k0 + cd);
        }
        #pragma unroll
        for (int p = 0; p < 8; p++) {
            const int c   = t + p * 128;
            const int row = c >> 3;
            const int cd  = (c & 7) * 8;
            cp16(wu + (row * GO_AS_STR + cd) * 2, g_Wot + (size_t)row * ALLD + k0 + cd);
        }
        asm volatile("cp.async.commit_group;" ::: "memory");
    };

    stage(0, 0);

    float acc[2][4][4];
    #pragma unroll
    for (int jm = 0; jm < 2; jm++)
        #pragma unroll
        for (int jn = 0; jn < 4; jn++) {
            acc[jm][jn][0]=0.f; acc[jm][jn][1]=0.f; acc[jm][jn][2]=0.f; acc[jm][jn][3]=0.f;
        }

    for (int kt = 0; kt < 32; kt++) {
        const int buf = kt & 1;
        asm volatile("cp.async.wait_group 0;" ::: "memory");
        __syncthreads();

        if (kt + 1 < 32) stage(kt + 1, buf ^ 1);

        const __half* as = (const __half*)(sm + GO_SM_A(buf));
        const __half* ws = (const __half*)(sm + GO_SM_W(buf));

        #pragma unroll
        for (int s = 0; s < 4; s++) {
            const int kc = 16 * s + 2 * tg;
            unsigned a[2][4];
            #pragma unroll
            for (int jm = 0; jm < 2; jm++) {
                a[jm][0] = *(const unsigned*)&as[(16 * jm + g)     * GO_AS_STR + kc];
                a[jm][1] = *(const unsigned*)&as[(16 * jm + g + 8) * GO_AS_STR + kc];
                a[jm][2] = *(const unsigned*)&as[(16 * jm + g)     * GO_AS_STR + kc + 8];
                a[jm][3] = *(const unsigned*)&as[(16 * jm + g + 8) * GO_AS_STR + kc + 8];
            }
            #pragma unroll
            for (int jn = 0; jn < 4; jn++) {
                const int n = 32 * warp + 8 * jn + g;
                const unsigned b0 = *(const unsigned*)&ws[n * GO_AS_STR + kc];
                const unsigned b1 = *(const unsigned*)&ws[n * GO_AS_STR + kc + 8];
                #pragma unroll
                for (int jm = 0; jm < 2; jm++)
                    mma16(acc[jm][jn], a[jm][0], a[jm][1], a[jm][2], a[jm][3], b0, b1);
            }
        }
        __syncthreads();
    }

    #pragma unroll
    for (int jm = 0; jm < 2; jm++) {
        const int row0 = r0 + 16 * jm + g;
        const int row1 = row0 + 8;
        #pragma unroll
        for (int jn = 0; jn < 4; jn++) {
            const int col = 32 * warp + 8 * jn + 2 * tg;
            const float bb0 = bo[col], bb1 = bo[col + 1];
            float2 w0, w1;
            w0.x = acc[jm][jn][0] + bb0;  w0.y = acc[jm][jn][1] + bb1;
            w1.x = acc[jm][jn][2] + bb0;  w1.y = acc[jm][jn][3] + bb1;
            *(float2*)&out[(size_t)row0 * DD + col] = w0;
            *(float2*)&out[(size_t)row1 * DD + col] = w1;
        }
    }
}

// ---------------------------------------------------------------------------
extern "C" void kernel_launch(void* const* d_in, const int* in_sizes, int n_in,
                              void* d_out, int out_size)
{
    const float* x    = (const float*)d_in[0];
    const int*   mask = (const int*)  d_in[1];
    const float* Wq   = (const float*)d_in[2];
    const float* bq   = (const float*)d_in[3];
    const float* Wk   = (const float*)d_in[4];
    const float* bk   = (const float*)d_in[5];
    const float* Wv   = (const float*)d_in[6];
    const float* bv   = (const float*)d_in[7];
    const float* Wo   = (const float*)d_in[8];
    const float* bo   = (const float*)d_in[9];
    float* out = (float*)d_out;

    convert_kernel<<<(N_CVT + 255) / 256, 256>>>(x, Wq, Wk, Wv, Wo);

    cudaFuncSetAttribute((const void*)gemm_qkv_kernel,
                         cudaFuncAttributeMaxDynamicSharedMemorySize,
                         GQ_XS_BYTES + GQ_WS_BYTES);
    gemm_qkv_kernel<<<dim3(64, 48), 128, GQ_XS_BYTES + GQ_WS_BYTES>>>(bq, bk, bv);

    transpose_v_kernel<<<BB * HH * 32, 256>>>();

    cudaFuncSetAttribute((const void*)attn_fp16_kernel,
                         cudaFuncAttributeMaxDynamicSharedMemorySize, ATT_SMEM);
    attn_fp16_kernel<<<BB * HH * (NN / BQ), 128, ATT_SMEM>>>(mask);

    cudaFuncSetAttribute((const void*)gemm_out_kernel,
                         cudaFuncAttributeMaxDynamicSharedMemorySize, GO_SMEM);
    gemm_out_kernel<<<BN / 32, 128, GO_SMEM>>>(bo, out);
}

// round 11
// speedup vs baseline: 2.5955x; 2.5955x over previous
#include <cuda_runtime.h>
#include <cuda_fp16.h>
#include <math.h>

#define BB 2
#define NN 2048
#define DD 128
#define HH 16
#define ALLD 2048
#define BN  4096

#define BQ 64          // q rows per attention block (4 warps x 16)
#define TK 64          // keys per tile

#define KS_STR 136     // halves per K row
#define VT_STR 72      // halves per V^T row

// Scratch
__device__ __half g_xh [BN*DD];
__device__ __half g_Wt [3*ALLD*DD];
__device__ __half g_Wot[DD*ALLD];
__device__ __half g_Qh [BB*HH*NN*DD];   // [bh][n][d], pre-scaled
__device__ __half g_Kh [BB*HH*NN*DD];   // [bh][n][d]
__device__ __half g_Vh [BB*HH*NN*DD];   // [bh][n][d]
__device__ __half g_Kc [BB*HH*NN*DD];   // compacted K [bh][j][d]
__device__ __half g_Vtc[BB*HH*DD*NN];   // compacted V^T [bh][d][j]
__device__ __half g_Ch [BB*NN*ALLD];    // ctx [n][ALLD]
__device__ int    g_idx[BB*NN];         // valid-token indices (padded with 0)
__device__ int    g_cnt[BB];

__device__ __forceinline__ unsigned h2pack(float x, float y) {
    __half2 h = __floats2half2_rn(x, y);
    return *(unsigned*)&h;
}

__device__ __forceinline__ void mma16(float* c,
                                      unsigned a0, unsigned a1, unsigned a2, unsigned a3,
                                      unsigned b0, unsigned b1) {
    asm volatile(
        "mma.sync.aligned.m16n8k16.row.col.f32.f16.f16.f32 "
        "{%0,%1,%2,%3}, {%4,%5,%6,%7}, {%8,%9}, {%0,%1,%2,%3};"
        : "+f"(c[0]), "+f"(c[1]), "+f"(c[2]), "+f"(c[3])
        : "r"(a0), "r"(a1), "r"(a2), "r"(a3), "r"(b0), "r"(b1));
}

__device__ __forceinline__ void cp16(unsigned dst, const void* src) {
    asm volatile("cp.async.cg.shared.global [%0], [%1], 16;" :: "r"(dst), "l"(src));
}

#define SCQ 0.08838834764831845f   // 1/sqrt(128)

// ---------------------------------------------------------------------------
// Kernel 0: convert x and weights to half (weights transposed, SC folded).
// ---------------------------------------------------------------------------
#define N_XH  (BN*DD)
#define N_WT  (3*ALLD*DD)
#define N_WOT (DD*ALLD)
#define N_CVT (N_XH + N_WT + N_WOT)

__global__ __launch_bounds__(256)
void convert_kernel(const float* __restrict__ x,
                    const float* __restrict__ Wq,
                    const float* __restrict__ Wk,
                    const float* __restrict__ Wv,
                    const float* __restrict__ Wo)
{
    const int idx = blockIdx.x * 256 + threadIdx.x;
    if (idx < N_XH) {
        g_xh[idx] = __float2half_rn(x[idx]);
    } else if (idx < N_XH + N_WT) {
        const int i = idx - N_XH;
        const int r = i >> 7;
        const int k = i & 127;
        const int proj = r >> 11;
        const int c    = r & 2047;
        const float v = (proj == 0) ? Wq[k * ALLD + c] * SCQ
                      : (proj == 1) ? Wk[k * ALLD + c]
                                    : Wv[k * ALLD + c];
        g_Wt[i] = __float2half_rn(v);
    } else if (idx < N_CVT) {
        const int i = idx - N_XH - N_WT;
        const int n = i >> 11;
        const int k = i & 2047;
        g_Wot[i] = __float2half_rn(Wo[k * DD + n]);
    }
}

// ---------------------------------------------------------------------------
// Kernel 0b: compact valid token indices per batch. grid BB, 256 threads.
// ---------------------------------------------------------------------------
__global__ __launch_bounds__(256)
void compact_kernel(const int* __restrict__ mask)
{
    __shared__ int cnts[256];
    __shared__ int offs[256];

    const int b = blockIdx.x;
    const int t = threadIdx.x;
    const int base = t * 8;

    int mloc[8];
    int c = 0;
    #pragma unroll
    for (int i = 0; i < 8; i++) {
        mloc[i] = mask[b * NN + base + i];
        c += (mloc[i] != 0);
    }
    cnts[t] = c;
    __syncthreads();

    if (t == 0) {
        int run = 0;
        for (int i = 0; i < 256; i++) { offs[i] = run; run += cnts[i]; }
        g_cnt[b] = run;
    }
    __syncthreads();

    int o = offs[t];
    #pragma unroll
    for (int i = 0; i < 8; i++)
        if (mloc[i]) g_idx[b * NN + (o++)] = base + i;

    __syncthreads();
    const int cnt = g_cnt[b];
    for (int i = cnt + t; i < NN; i += 256) g_idx[b * NN + i] = 0;
}

// ---------------------------------------------------------------------------
// Kernel 1: QKV projection as fp16 MMA GEMM.
// ---------------------------------------------------------------------------
#define GQ_XS_STR 136
#define GQ_XS_BYTES (64 * GQ_XS_STR * 2)
#define GQ_WS_BYTES (128 * GQ_XS_STR * 2)

__global__ __launch_bounds__(128)
void gemm_qkv_kernel(const float* __restrict__ bq,
                     const float* __restrict__ bk,
                     const float* __restrict__ bv)
{
    extern __shared__ char sm[];
    __half* xs = (__half*)sm;
    __half* ws = (__half*)(sm + GQ_XS_BYTES);

    const int r0 = blockIdx.x * 64;
    const int n0 = blockIdx.y * 128;
    const int proj = n0 >> 11;
    const int h    = (n0 >> 7) & 15;

    const int t    = threadIdx.x;
    const int warp = t >> 5;
    const int lane = t & 31;
    const int g    = lane >> 2;
    const int tg   = lane & 3;
    const int m0   = warp * 16;

    const unsigned smu = (unsigned)__cvta_generic_to_shared(sm);

    #pragma unroll
    for (int p = 0; p < 8; p++) {
        const int c   = t + p * 128;
        const int row = c >> 4;
        const int cd  = (c & 15) * 8;
        cp16(smu + (row * GQ_XS_STR + cd) * 2, g_xh + (size_t)(r0 + row) * DD + cd);
    }
    #pragma unroll
    for (int p = 0; p < 16; p++) {
        const int c   = t + p * 128;
        const int row = c >> 4;
        const int cd  = (c & 15) * 8;
        cp16(smu + GQ_XS_BYTES + (row * GQ_XS_STR + cd) * 2,
             g_Wt + (size_t)(n0 + row) * DD + cd);
    }
    asm volatile("cp.async.commit_group;" ::: "memory");
    asm volatile("cp.async.wait_group 0;" ::: "memory");
    __syncthreads();

    float acc[16][4];
    #pragma unroll
    for (int j = 0; j < 16; j++) { acc[j][0]=0.f; acc[j][1]=0.f; acc[j][2]=0.f; acc[j][3]=0.f; }

    #pragma unroll
    for (int s = 0; s < 8; s++) {
        const int kc = 16 * s + 2 * tg;
        const unsigned a0 = *(const unsigned*)&xs[(m0 + g)     * GQ_XS_STR + kc];
        const unsigned a1 = *(const unsigned*)&xs[(m0 + g + 8) * GQ_XS_STR + kc];
        const unsigned a2 = *(const unsigned*)&xs[(m0 + g)     * GQ_XS_STR + kc + 8];
        const unsigned a3 = *(const unsigned*)&xs[(m0 + g + 8) * GQ_XS_STR + kc + 8];
        #pragma unroll
        for (int j = 0; j < 16; j++) {
            const unsigned b0 = *(const unsigned*)&ws[(8 * j + g) * GQ_XS_STR + kc];
            const unsigned b1 = *(const unsigned*)&ws[(8 * j + g) * GQ_XS_STR + kc + 8];
            mma16(acc[j], a0, a1, a2, a3, b0, b1);
        }
    }

    const float* bias = (proj == 0) ? bq : (proj == 1) ? bk : bv;
    const float  bscl = (proj == 0) ? SCQ : 1.0f;
    __half* dst = (proj == 0) ? g_Qh : (proj == 1) ? g_Kh : g_Vh;
    const int bcol = n0 & 2047;

    const int row0 = r0 + m0 + g;
    const int row1 = row0 + 8;
    const int b0i  = row0 >> 11, nn0 = row0 & 2047;
    const int b1i  = row1 >> 11, nn1 = row1 & 2047;
    __half* d0 = dst + (((size_t)(b0i * HH + h)) * NN + nn0) * DD;
    __half* d1 = dst + (((size_t)(b1i * HH + h)) * NN + nn1) * DD;

    #pragma unroll
    for (int j = 0; j < 16; j++) {
        const int ci = 8 * j + 2 * tg;
        const float bb0 = bias[bcol + ci]     * bscl;
        const float bb1 = bias[bcol + ci + 1] * bscl;
        *(unsigned*)&d0[ci] = h2pack(acc[j][0] + bb0, acc[j][1] + bb1);
        *(unsigned*)&d1[ci] = h2pack(acc[j][2] + bb0, acc[j][3] + bb1);
    }
}

// ---------------------------------------------------------------------------
// Kernel 1b: gather compacted K.  grid (BB*HH*32), 256 thr.
// ---------------------------------------------------------------------------
__global__ __launch_bounds__(256)
void gather_k_kernel()
{
    const int bh = blockIdx.x >> 5;
    const int jt = blockIdx.x & 31;
    const int j0 = jt * 64;
    const int b  = bh >> 4;
    if (j0 >= g_cnt[b]) return;

    const int t = threadIdx.x;
    const int* idx = g_idx + b * NN;
    #pragma unroll
    for (int p = 0; p < 4; p++) {
        const int c   = t + p * 256;
        const int row = c >> 4;
        const int cd  = (c & 15) * 8;
        *(uint4*)&g_Kc[((size_t)bh * NN + j0 + row) * DD + cd] =
            *(const uint4*)&g_Kh[((size_t)bh * NN + idx[j0 + row]) * DD + cd];
    }
}

// ---------------------------------------------------------------------------
// Kernel 1c: gather + transpose V.  Vtc[bh][d][j] = Vh[bh][idx[j]][d].
// ---------------------------------------------------------------------------
__global__ __launch_bounds__(256)
void gather_tv_kernel()
{
    __shared__ __half ts[64 * 136];

    const int bh = blockIdx.x >> 5;
    const int jt = blockIdx.x & 31;
    const int j0 = jt * 64;
    const int b  = bh >> 4;
    if (j0 >= g_cnt[b]) return;

    const int t = threadIdx.x;
    const int* idx = g_idx + b * NN;

    #pragma unroll
    for (int p = 0; p < 4; p++) {
        const int c   = t + p * 256;
        const int row = c >> 4;
        const int cd  = (c & 15) * 8;
        *(uint4*)&ts[row * 136 + cd] =
            *(const uint4*)&g_Vh[((size_t)bh * NN + idx[j0 + row]) * DD + cd];
    }
    __syncthreads();

    const int d  = t >> 1;
    const int hn = (t & 1) * 32;
    __half* dst = g_Vtc + ((size_t)bh * DD + d) * NN + j0 + hn;
    #pragma unroll
    for (int c = 0; c < 32; c += 2) {
        const int n = hn + c;
        *(unsigned*)&dst[c] = h2pack(__half2float(ts[n * 136 + d]),
                                     __half2float(ts[(n + 1) * 136 + d]));
    }
}

// ---------------------------------------------------------------------------
// Kernel 1d: zero ctx rows for masked queries. grid BN, 256 thr.
// ---------------------------------------------------------------------------
__global__ __launch_bounds__(256)
void zero_ctx_kernel(const int* __restrict__ mask)
{
    const int row = blockIdx.x;
    if (mask[row]) return;
    uint4 z; z.x = 0; z.y = 0; z.z = 0; z.w = 0;
    ((uint4*)(g_Ch + (size_t)row * ALLD))[threadIdx.x] = z;
}

// ---------------------------------------------------------------------------
// Kernel 2: flash attention over compacted q/k (round-8 scalar-LDS core).
// ---------------------------------------------------------------------------
#define KS_BYTES (TK * KS_STR * 2)
#define VT_BYTES (DD * VT_STR * 2)
#define SM_KS(buf)  ((buf) * KS_BYTES)
#define SM_VT(buf)  (2 * KS_BYTES + (buf) * VT_BYTES)
#define ATT_SMEM    (2 * KS_BYTES + 2 * VT_BYTES)

__global__ __launch_bounds__(128)
void attn_fp16_kernel()
{
    extern __shared__ char sm[];

    const int bid = blockIdx.x;
    const int qt  = bid & 31;
    const int bh  = bid >> 5;
    const int h   = bh & 15;
    const int b   = bh >> 4;
    const int n0  = qt * BQ;

    const int cnt = g_cnt[b];
    if (n0 >= cnt) return;

    const int t    = threadIdx.x;
    const int warp = t >> 5;
    const int lane = t & 31;
    const int g    = lane >> 2;
    const int tg   = lane & 3;
    const int m0   = warp * 16;

    const __half* Qh  = g_Qh  + (size_t)bh * NN * DD;
    const __half* Kc  = g_Kc  + (size_t)bh * NN * DD;
    const __half* Vtc = g_Vtc + (size_t)bh * DD * NN;
    const int*    idx = g_idx + b * NN;

    const unsigned smu = (unsigned)__cvta_generic_to_shared(sm);

    auto stage = [&](int kt, int buf) {
        const int k0 = kt * TK;
        const unsigned ksu = smu + SM_KS(buf);
        const unsigned vtu = smu + SM_VT(buf);
        #pragma unroll
        for (int p = 0; p < 8; p++) {
            const int c   = t + p * 128;
            const int row = c >> 4;
            const int cd  = (c & 15) * 8;
            cp16(ksu + (row * KS_STR + cd) * 2, Kc + (size_t)(k0 + row) * DD + cd);
        }
        #pragma unroll
        for (int p = 0; p < 8; p++) {
            const int c   = t + p * 128;
            const int row = c >> 3;
            const int cd  = (c & 7) * 8;
            cp16(vtu + (row * VT_STR + cd) * 2, Vtc + (size_t)row * NN + k0 + cd);
        }
        asm volatile("cp.async.commit_group;" ::: "memory");
    };

    // ---- Q fragments: gathered rows via index list ----
    const int qr0 = idx[n0 + m0 + g];
    const int qr1 = idx[n0 + m0 + g + 8];
    unsigned qa[8][4];
    {
        const __half* q0 = Qh + (size_t)qr0 * DD;
        const __half* q1 = Qh + (size_t)qr1 * DD;
        #pragma unroll
        for (int s = 0; s < 8; s++) {
            const int c = 16 * s + 2 * tg;
            qa[s][0] = *(const unsigned*)&q0[c];
            qa[s][1] = *(const unsigned*)&q1[c];
            qa[s][2] = *(const unsigned*)&q0[c + 8];
            qa[s][3] = *(const unsigned*)&q1[c + 8];
        }
    }

    const int NTc = (cnt + TK - 1) / TK;
    stage(0, 0);

    float o[16][4];
    #pragma unroll
    for (int j = 0; j < 16; j++) { o[j][0]=0.f; o[j][1]=0.f; o[j][2]=0.f; o[j][3]=0.f; }
    float l0 = 0.f, l1 = 0.f;

    for (int kt = 0; kt < NTc; kt++) {
        const int buf = kt & 1;
        const int k0  = kt * TK;
        asm volatile("cp.async.wait_group 0;" ::: "memory");
        __syncthreads();

        if (kt + 1 < NTc) stage(kt + 1, buf ^ 1);

        const __half* ks = (const __half*)(sm + SM_KS(buf));
        const __half* vt = (const __half*)(sm + SM_VT(buf));

        float sc[8][4];
        #pragma unroll
        for (int j = 0; j < 8; j++) { sc[j][0]=0.f; sc[j][1]=0.f; sc[j][2]=0.f; sc[j][3]=0.f; }

        #pragma unroll
        for (int s = 0; s < 8; s++) {
            const int dcol = 16 * s + 2 * tg;
            #pragma unroll
            for (int j = 0; j < 8; j++) {
                const unsigned b0 = *(const unsigned*)&ks[(8 * j + g) * KS_STR + dcol];
                const unsigned b1 = *(const unsigned*)&ks[(8 * j + g) * KS_STR + dcol + 8];
                mma16(sc[j], qa[s][0], qa[s][1], qa[s][2], qa[s][3], b0, b1);
            }
        }

        // ---- softmax; key validity = positional (compacted) ----
        unsigned pa[4][4];
        #pragma unroll
        for (int j = 0; j < 8; j++) {
            const int ci = 8 * j + 2 * tg;
            const bool v0 = (k0 + ci)     < cnt;
            const bool v1 = (k0 + ci + 1) < cnt;
            const float e0 = v0 ? __expf(sc[j][0]) : 0.f;
            const float e1 = v1 ? __expf(sc[j][1]) : 0.f;
            const float e2 = v0 ? __expf(sc[j][2]) : 0.f;
            const float e3 = v1 ? __expf(sc[j][3]) : 0.f;
            l0 += e0 + e1;
            l1 += e2 + e3;
            const unsigned h01 = h2pack(e0, e1);
            const unsigned h23 = h2pack(e2, e3);
            const int s2 = j >> 1;
            if ((j & 1) == 0) { pa[s2][0] = h01; pa[s2][1] = h23; }
            else              { pa[s2][2] = h01; pa[s2][3] = h23; }
        }

        #pragma unroll
        for (int s2 = 0; s2 < 4; s2++) {
            const int kcol = 16 * s2 + 2 * tg;
            #pragma unroll
            for (int j2 = 0; j2 < 16; j2++) {
                const unsigned b0 = *(const unsigned*)&vt[(8 * j2 + g) * VT_STR + kcol];
                const unsigned b1 = *(const unsigned*)&vt[(8 * j2 + g) * VT_STR + kcol + 8];
                mma16(o[j2], pa[s2][0], pa[s2][1], pa[s2][2], pa[s2][3], b0, b1);
            }
        }
        __syncthreads();
    }

    l0 += __shfl_xor_sync(0xffffffffu, l0, 1);
    l0 += __shfl_xor_sync(0xffffffffu, l0, 2);
    l1 += __shfl_xor_sync(0xffffffffu, l1, 1);
    l1 += __shfl_xor_sync(0xffffffffu, l1, 2);

    const bool  val0 = (n0 + m0 + g)     < cnt;
    const bool  val1 = (n0 + m0 + g + 8) < cnt;
    const float inv0 = 1.0f / l0;
    const float inv1 = 1.0f / l1;

    __half* ctx0 = g_Ch + ((size_t)(b * NN + qr0)) * ALLD + h * DD;
    __half* ctx1 = g_Ch + ((size_t)(b * NN + qr1)) * ALLD + h * DD;
    #pragma unroll
    for (int j2 = 0; j2 < 16; j2++) {
        const int ci = 8 * j2 + 2 * tg;
        if (val0) *(unsigned*)&ctx0[ci] = h2pack(o[j2][0] * inv0, o[j2][1] * inv0);
        if (val1) *(unsigned*)&ctx1[ci] = h2pack(o[j2][2] * inv1, o[j2][3] * inv1);
    }
}

// ---------------------------------------------------------------------------
// Kernel 3: output projection as fp16 MMA GEMM.
// ---------------------------------------------------------------------------
#define GO_AS_STR 72
#define GO_AS_BYTES (32 * GO_AS_STR * 2)
#define GO_WS_BYTES (128 * GO_AS_STR * 2)
#define GO_SM_A(buf) ((buf) * (GO_AS_BYTES + GO_WS_BYTES))
#define GO_SM_W(buf) (GO_SM_A(buf) + GO_AS_BYTES)
#define GO_SMEM (2 * (GO_AS_BYTES + GO_WS_BYTES))

__global__ __launch_bounds__(128)
void gemm_out_kernel(const float* __restrict__ bo, float* __restrict__ out)
{
    extern __shared__ char sm[];

    const int r0   = blockIdx.x * 32;
    const int t    = threadIdx.x;
    const int warp = t >> 5;
    const int lane = t & 31;
    const int g    = lane >> 2;
    const int tg   = lane & 3;

    const unsigned smu = (unsigned)__cvta_generic_to_shared(sm);

    auto stage = [&](int kt, int buf) {
        const int k0 = kt * 64;
        const unsigned au = smu + GO_SM_A(buf);
        const unsigned wu = smu + GO_SM_W(buf);
        #pragma unroll
        for (int p = 0; p < 2; p++) {
            const int c   = t + p * 128;
            const int row = c >> 3;
            const int cd  = (c & 7) * 8;
            cp16(au + (row * GO_AS_STR + cd) * 2, g_Ch + (size_t)(r0 + row) * ALLD + k0 + cd);
        }
        #pragma unroll
        for (int p = 0; p < 8; p++) {
            const int c   = t + p * 128;
            const int row = c >> 3;
            const int cd  = (c & 7) * 8;
            cp16(wu + (row * GO_AS_STR + cd) * 2, g_Wot + (size_t)row * ALLD + k0 + cd);
        }
        asm volatile("cp.async.commit_group;" ::: "memory");
    };

    stage(0, 0);

    float acc[2][4][4];
    #pragma unroll
    for (int jm = 0; jm < 2; jm++)
        #pragma unroll
        for (int jn = 0; jn < 4; jn++) {
            acc[jm][jn][0]=0.f; acc[jm][jn][1]=0.f; acc[jm][jn][2]=0.f; acc[jm][jn][3]=0.f;
        }

    for (int kt = 0; kt < 32; kt++) {
        const int buf = kt & 1;
        asm volatile("cp.async.wait_group 0;" ::: "memory");
        __syncthreads();

        if (kt + 1 < 32) stage(kt + 1, buf ^ 1);

        const __half* as = (const __half*)(sm + GO_SM_A(buf));
        const __half* ws = (const __half*)(sm + GO_SM_W(buf));

        #pragma unroll
        for (int s = 0; s < 4; s++) {
            const int kc = 16 * s + 2 * tg;
            unsigned a[2][4];
            #pragma unroll
            for (int jm = 0; jm < 2; jm++) {
                a[jm][0] = *(const unsigned*)&as[(16 * jm + g)     * GO_AS_STR + kc];
                a[jm][1] = *(const unsigned*)&as[(16 * jm + g + 8) * GO_AS_STR + kc];
                a[jm][2] = *(const unsigned*)&as[(16 * jm + g)     * GO_AS_STR + kc + 8];
                a[jm][3] = *(const unsigned*)&as[(16 * jm + g + 8) * GO_AS_STR + kc + 8];
            }
            #pragma unroll
            for (int jn = 0; jn < 4; jn++) {
                const int n = 32 * warp + 8 * jn + g;
                const unsigned b0 = *(const unsigned*)&ws[n * GO_AS_STR + kc];
                const unsigned b1 = *(const unsigned*)&ws[n * GO_AS_STR + kc + 8];
                #pragma unroll
                for (int jm = 0; jm < 2; jm++)
                    mma16(acc[jm][jn], a[jm][0], a[jm][1], a[jm][2], a[jm][3], b0, b1);
            }
        }
        __syncthreads();
    }

    #pragma unroll
    for (int jm = 0; jm < 2; jm++) {
        const int row0 = r0 + 16 * jm + g;
        const int row1 = row0 + 8;
        #pragma unroll
        for (int jn = 0; jn < 4; jn++) {
            const int col = 32 * warp + 8 * jn + 2 * tg;
            const float bb0 = bo[col], bb1 = bo[col + 1];
            float2 w0, w1;
            w0.x = acc[jm][jn][0] + bb0;  w0.y = acc[jm][jn][1] + bb1;
            w1.x = acc[jm][jn][2] + bb0;  w1.y = acc[jm][jn][3] + bb1;
            *(float2*)&out[(size_t)row0 * DD + col] = w0;
            *(float2*)&out[(size_t)row1 * DD + col] = w1;
        }
    }
}

// ---------------------------------------------------------------------------
extern "C" void kernel_launch(void* const* d_in, const int* in_sizes, int n_in,
                              void* d_out, int out_size)
{
    const float* x    = (const float*)d_in[0];
    const int*   mask = (const int*)  d_in[1];
    const float* Wq   = (const float*)d_in[2];
    const float* bq   = (const float*)d_in[3];
    const float* Wk   = (const float*)d_in[4];
    const float* bk   = (const float*)d_in[5];
    const float* Wv   = (const float*)d_in[6];
    const float* bv   = (const float*)d_in[7];
    const float* Wo   = (const float*)d_in[8];
    const float* bo   = (const float*)d_in[9];
    float* out = (float*)d_out;

    convert_kernel<<<(N_CVT + 255) / 256, 256>>>(x, Wq, Wk, Wv, Wo);
    compact_kernel<<<BB, 256>>>(mask);

    cudaFuncSetAttribute((const void*)gemm_qkv_kernel,
                         cudaFuncAttributeMaxDynamicSharedMemorySize,
                         GQ_XS_BYTES + GQ_WS_BYTES);
    gemm_qkv_kernel<<<dim3(64, 48), 128, GQ_XS_BYTES + GQ_WS_BYTES>>>(bq, bk, bv);

    gather_k_kernel<<<BB * HH * 32, 256>>>();
    gather_tv_kernel<<<BB * HH * 32, 256>>>();
    zero_ctx_kernel<<<BN, 256>>>(mask);

    cudaFuncSetAttribute((const void*)attn_fp16_kernel,
                         cudaFuncAttributeMaxDynamicSharedMemorySize, ATT_SMEM);
    attn_fp16_kernel<<<BB * HH * 32, 128, ATT_SMEM>>>();

    cudaFuncSetAttribute((const void*)gemm_out_kernel,
                         cudaFuncAttributeMaxDynamicSharedMemorySize, GO_SMEM);
    gemm_out_kernel<<<BN / 32, 128, GO_SMEM>>>(bo, out);
}

// round 13
// speedup vs baseline: 3.0082x; 1.1590x over previous
#include <cuda_runtime.h>
#include <cuda_fp16.h>
#include <math.h>

#define BB 2
#define NN 2048
#define DD 128
#define HH 16
#define ALLD 2048
#define BN  4096

#define BQ 64          // q rows per attention block (4 warps x 16)
#define TK 64          // keys per tile

#define KS_STR 136     // halves per K row
#define VT_STR 72      // halves per V^T row

// Scratch (zero-initialized device globals; tails beyond cnt are never
// written and therefore stay zero — guarded stores keep it that way)
__device__ __half g_xc [BN*DD];         // compacted x as half [b][j][d]
__device__ __half g_Wt [3*ALLD*DD];     // W{q,k,v}^T half [n][k], SC in Wq
__device__ __half g_Wot[DD*ALLD];       // Wo^T half [n][k]
__device__ __half g_Qc [BB*HH*NN*DD];   // compacted Q [bh][j][d], pre-scaled
__device__ __half g_Kc [BB*HH*NN*DD];   // compacted K [bh][j][d]
__device__ __half g_Vc [BB*HH*NN*DD];   // compacted V [bh][j][d]
__device__ __half g_Vtc[BB*HH*DD*NN];   // compacted V^T [bh][d][j]
__device__ __half g_Chc[BB*NN*ALLD];    // compacted ctx [b][j][ALLD]
__device__ int    g_idx[BB*NN];         // valid-token indices
__device__ int    g_cnt[BB];

__device__ __forceinline__ unsigned h2pack(float x, float y) {
    __half2 h = __floats2half2_rn(x, y);
    return *(unsigned*)&h;
}

__device__ __forceinline__ void mma16(float* c,
                                      unsigned a0, unsigned a1, unsigned a2, unsigned a3,
                                      unsigned b0, unsigned b1) {
    asm volatile(
        "mma.sync.aligned.m16n8k16.row.col.f32.f16.f16.f32 "
        "{%0,%1,%2,%3}, {%4,%5,%6,%7}, {%8,%9}, {%0,%1,%2,%3};"
        : "+f"(c[0]), "+f"(c[1]), "+f"(c[2]), "+f"(c[3])
        : "r"(a0), "r"(a1), "r"(a2), "r"(a3), "r"(b0), "r"(b1));
}

__device__ __forceinline__ void cp16(unsigned dst, const void* src) {
    asm volatile("cp.async.cg.shared.global [%0], [%1], 16;" :: "r"(dst), "l"(src));
}

#define SCQ 0.08838834764831845f   // 1/sqrt(128)

// ---------------------------------------------------------------------------
// Kernel 0: compact valid token indices per batch. grid BB, 256 threads.
// ---------------------------------------------------------------------------
__global__ __launch_bounds__(256)
void compact_kernel(const int* __restrict__ mask)
{
    __shared__ int cnts[256];
    __shared__ int offs[256];

    const int b = blockIdx.x;
    const int t = threadIdx.x;
    const int base = t * 8;

    int mloc[8];
    int c = 0;
    #pragma unroll
    for (int i = 0; i < 8; i++) {
        mloc[i] = mask[b * NN + base + i];
        c += (mloc[i] != 0);
    }
    cnts[t] = c;
    __syncthreads();

    if (t == 0) {
        int run = 0;
        for (int i = 0; i < 256; i++) { offs[i] = run; run += cnts[i]; }
        g_cnt[b] = run;
    }
    __syncthreads();

    int o = offs[t];
    #pragma unroll
    for (int i = 0; i < 8; i++)
        if (mloc[i]) g_idx[b * NN + (o++)] = base + i;

    __syncthreads();
    const int cnt = g_cnt[b];
    for (int i = cnt + t; i < NN; i += 256) g_idx[b * NN + i] = 0;
}

// ---------------------------------------------------------------------------
// Kernel 1: convert weights to half; gather x into compacted xc (half).
// ---------------------------------------------------------------------------
#define N_XH  (BN*DD)
#define N_WT  (3*ALLD*DD)
#define N_WOT (DD*ALLD)
#define N_CVT (N_XH + N_WT + N_WOT)

__global__ __launch_bounds__(256)
void convert_kernel(const float* __restrict__ x,
                    const float* __restrict__ Wq,
                    const float* __restrict__ Wk,
                    const float* __restrict__ Wv,
                    const float* __restrict__ Wo)
{
    const int idx = blockIdx.x * 256 + threadIdx.x;
    if (idx < N_XH) {
        const int r = idx >> 7;
        const int d = idx & 127;
        const int b = r >> 11;
        const int j = r & 2047;
        if (j < g_cnt[b])
            g_xc[idx] = __float2half_rn(
                x[((size_t)(b * NN + g_idx[b * NN + j])) * DD + d]);
    } else if (idx < N_XH + N_WT) {
        const int i = idx - N_XH;
        const int r = i >> 7;
        const int k = i & 127;
        const int proj = r >> 11;
        const int c    = r & 2047;
        const float v = (proj == 0) ? Wq[k * ALLD + c] * SCQ
                      : (proj == 1) ? Wk[k * ALLD + c]
                                    : Wv[k * ALLD + c];
        g_Wt[i] = __float2half_rn(v);
    } else if (idx < N_CVT) {
        const int i = idx - N_XH - N_WT;
        const int n = i >> 11;
        const int k = i & 2047;
        g_Wot[i] = __float2half_rn(Wo[k * DD + n]);
    }
}

// ---------------------------------------------------------------------------
// Kernel 2: QKV projection over compacted rows (fp16 MMA).
// grid (BB*32, 48); block = 64 compacted rows x 128 cols; early exit.
// ---------------------------------------------------------------------------
#define GQ_XS_STR 136
#define GQ_XS_BYTES (64 * GQ_XS_STR * 2)
#define GQ_WS_BYTES (128 * GQ_XS_STR * 2)

__global__ __launch_bounds__(128)
void gemm_qkv_kernel(const float* __restrict__ bq,
                     const float* __restrict__ bk,
                     const float* __restrict__ bv)
{
    extern __shared__ char sm[];
    __half* xs = (__half*)sm;
    __half* ws = (__half*)(sm + GQ_XS_BYTES);

    const int b  = blockIdx.x >> 5;
    const int j0 = (blockIdx.x & 31) * 64;
    const int cnt = g_cnt[b];
    if (j0 >= cnt) return;

    const int n0 = blockIdx.y * 128;
    const int proj = n0 >> 11;
    const int h    = (n0 >> 7) & 15;

    const int t    = threadIdx.x;
    const int warp = t >> 5;
    const int lane = t & 31;
    const int g    = lane >> 2;
    const int tg   = lane & 3;
    const int m0   = warp * 16;

    const unsigned smu = (unsigned)__cvta_generic_to_shared(sm);

    #pragma unroll
    for (int p = 0; p < 8; p++) {
        const int c   = t + p * 128;
        const int row = c >> 4;
        const int cd  = (c & 15) * 8;
        cp16(smu + (row * GQ_XS_STR + cd) * 2,
             g_xc + ((size_t)(b * NN + j0 + row)) * DD + cd);
    }
    #pragma unroll
    for (int p = 0; p < 16; p++) {
        const int c   = t + p * 128;
        const int row = c >> 4;
        const int cd  = (c & 15) * 8;
        cp16(smu + GQ_XS_BYTES + (row * GQ_XS_STR + cd) * 2,
             g_Wt + (size_t)(n0 + row) * DD + cd);
    }
    asm volatile("cp.async.commit_group;" ::: "memory");
    asm volatile("cp.async.wait_group 0;" ::: "memory");
    __syncthreads();

    float acc[16][4];
    #pragma unroll
    for (int j = 0; j < 16; j++) { acc[j][0]=0.f; acc[j][1]=0.f; acc[j][2]=0.f; acc[j][3]=0.f; }

    #pragma unroll
    for (int s = 0; s < 8; s++) {
        const int kc = 16 * s + 2 * tg;
        const unsigned a0 = *(const unsigned*)&xs[(m0 + g)     * GQ_XS_STR + kc];
        const unsigned a1 = *(const unsigned*)&xs[(m0 + g + 8) * GQ_XS_STR + kc];
        const unsigned a2 = *(const unsigned*)&xs[(m0 + g)     * GQ_XS_STR + kc + 8];
        const unsigned a3 = *(const unsigned*)&xs[(m0 + g + 8) * GQ_XS_STR + kc + 8];
        #pragma unroll
        for (int j = 0; j < 16; j++) {
            const unsigned b0 = *(const unsigned*)&ws[(8 * j + g) * GQ_XS_STR + kc];
            const unsigned b1 = *(const unsigned*)&ws[(8 * j + g) * GQ_XS_STR + kc + 8];
            mma16(acc[j], a0, a1, a2, a3, b0, b1);
        }
    }

    const float* bias = (proj == 0) ? bq : (proj == 1) ? bk : bv;
    const float  bscl = (proj == 0) ? SCQ : 1.0f;
    __half* dst = (proj == 0) ? g_Qc : (proj == 1) ? g_Kc : g_Vc;
    const int bcol = n0 & 2047;

    const int row0 = j0 + m0 + g;        // local compacted row
    const int row1 = row0 + 8;
    const int bh   = b * HH + h;
    __half* d0 = dst + ((size_t)bh * NN + row0) * DD;
    __half* d1 = dst + ((size_t)bh * NN + row1) * DD;
    const bool s0ok = row0 < cnt;
    const bool s1ok = row1 < cnt;

    #pragma unroll
    for (int j = 0; j < 16; j++) {
        const int ci = 8 * j + 2 * tg;
        const float bb0 = bias[bcol + ci]     * bscl;
        const float bb1 = bias[bcol + ci + 1] * bscl;
        if (s0ok) *(unsigned*)&d0[ci] = h2pack(acc[j][0] + bb0, acc[j][1] + bb1);
        if (s1ok) *(unsigned*)&d1[ci] = h2pack(acc[j][2] + bb0, acc[j][3] + bb1);
    }
}

// ---------------------------------------------------------------------------
// Kernel 3: transpose compacted V.  Vtc[bh][d][j] = Vc[bh][j][d].
// grid (BB*HH*32), 256 thr; early exit.
// ---------------------------------------------------------------------------
__global__ __launch_bounds__(256)
void transpose_v_kernel()
{
    __shared__ __half ts[64 * 136];

    const int bh = blockIdx.x >> 5;
    const int jt = blockIdx.x & 31;
    const int j0 = jt * 64;
    const int b  = bh >> 4;
    if (j0 >= g_cnt[b]) return;

    const int t = threadIdx.x;
    const __half* src = g_Vc + ((size_t)bh * NN + j0) * DD;

    #pragma unroll
    for (int p = 0; p < 4; p++) {
        const int c   = t + p * 256;
        const int row = c >> 4;
        const int cd  = (c & 15) * 8;
        *(uint4*)&ts[row * 136 + cd] = *(const uint4*)&src[(size_t)row * DD + cd];
    }
    __syncthreads();

    const int d  = t >> 1;
    const int hn = (t & 1) * 32;
    __half* dst = g_Vtc + ((size_t)bh * DD + d) * NN + j0 + hn;
    #pragma unroll
    for (int c = 0; c < 32; c += 2) {
        const int n = hn + c;
        *(unsigned*)&dst[c] = h2pack(__half2float(ts[n * 136 + d]),
                                     __half2float(ts[(n + 1) * 136 + d]));
    }
}

// ---------------------------------------------------------------------------
// Kernel 4: flash attention over compacted q/k/v.
// ---------------------------------------------------------------------------
#define KS_BYTES (TK * KS_STR * 2)
#define VT_BYTES (DD * VT_STR * 2)
#define SM_KS(buf)  ((buf) * KS_BYTES)
#define SM_VT(buf)  (2 * KS_BYTES + (buf) * VT_BYTES)
#define ATT_SMEM    (2 * KS_BYTES + 2 * VT_BYTES)

__global__ __launch_bounds__(128)
void attn_fp16_kernel()
{
    extern __shared__ char sm[];

    const int bid = blockIdx.x;
    const int qt  = bid & 31;
    const int bh  = bid >> 5;
    const int b   = bh >> 4;
    const int n0  = qt * BQ;

    const int cnt = g_cnt[b];
    if (n0 >= cnt) return;

    const int t    = threadIdx.x;
    const int warp = t >> 5;
    const int lane = t & 31;
    const int g    = lane >> 2;
    const int tg   = lane & 3;
    const int m0   = warp * 16;

    const __half* Qc  = g_Qc  + (size_t)bh * NN * DD;
    const __half* Kc  = g_Kc  + (size_t)bh * NN * DD;
    const __half* Vtc = g_Vtc + (size_t)bh * DD * NN;

    const unsigned smu = (unsigned)__cvta_generic_to_shared(sm);

    auto stage = [&](int kt, int buf) {
        const int k0 = kt * TK;
        const unsigned ksu = smu + SM_KS(buf);
        const unsigned vtu = smu + SM_VT(buf);
        #pragma unroll
        for (int p = 0; p < 8; p++) {
            const int c   = t + p * 128;
            const int row = c >> 4;
            const int cd  = (c & 15) * 8;
            cp16(ksu + (row * KS_STR + cd) * 2, Kc + (size_t)(k0 + row) * DD + cd);
        }
        #pragma unroll
        for (int p = 0; p < 8; p++) {
            const int c   = t + p * 128;
            const int row = c >> 3;
            const int cd  = (c & 7) * 8;
            cp16(vtu + (row * VT_STR + cd) * 2, Vtc + (size_t)row * NN + k0 + cd);
        }
        asm volatile("cp.async.commit_group;" ::: "memory");
    };

    // ---- Q fragments: direct compacted rows ----
    const int jr0 = n0 + m0 + g;
    const int jr1 = jr0 + 8;
    unsigned qa[8][4];
    {
        const __half* q0 = Qc + (size_t)jr0 * DD;
        const __half* q1 = Qc + (size_t)jr1 * DD;
        #pragma unroll
        for (int s = 0; s < 8; s++) {
            const int c = 16 * s + 2 * tg;
            qa[s][0] = *(const unsigned*)&q0[c];
            qa[s][1] = *(const unsigned*)&q1[c];
            qa[s][2] = *(const unsigned*)&q0[c + 8];
            qa[s][3] = *(const unsigned*)&q1[c + 8];
        }
    }

    const int NTc = (cnt + TK - 1) / TK;
    stage(0, 0);

    float o[16][4];
    #pragma unroll
    for (int j = 0; j < 16; j++) { o[j][0]=0.f; o[j][1]=0.f; o[j][2]=0.f; o[j][3]=0.f; }
    float l0 = 0.f, l1 = 0.f;

    for (int kt = 0; kt < NTc; kt++) {
        const int buf = kt & 1;
        const int k0  = kt * TK;
        asm volatile("cp.async.wait_group 0;" ::: "memory");
        __syncthreads();

        if (kt + 1 < NTc) stage(kt + 1, buf ^ 1);

        const __half* ks = (const __half*)(sm + SM_KS(buf));
        const __half* vt = (const __half*)(sm + SM_VT(buf));

        float sc[8][4];
        #pragma unroll
        for (int j = 0; j < 8; j++) { sc[j][0]=0.f; sc[j][1]=0.f; sc[j][2]=0.f; sc[j][3]=0.f; }

        #pragma unroll
        for (int s = 0; s < 8; s++) {
            const int dcol = 16 * s + 2 * tg;
            #pragma unroll
            for (int j = 0; j < 8; j++) {
                const unsigned b0 = *(const unsigned*)&ks[(8 * j + g) * KS_STR + dcol];
                const unsigned b1 = *(const unsigned*)&ks[(8 * j + g) * KS_STR + dcol + 8];
                mma16(sc[j], qa[s][0], qa[s][1], qa[s][2], qa[s][3], b0, b1);
            }
        }

        // ---- softmax; key validity = positional (compacted) ----
        unsigned pa[4][4];
        #pragma unroll
        for (int j = 0; j < 8; j++) {
            const int ci = 8 * j + 2 * tg;
            const bool v0 = (k0 + ci)     < cnt;
            const bool v1 = (k0 + ci + 1) < cnt;
            const float e0 = v0 ? __expf(sc[j][0]) : 0.f;
            const float e1 = v1 ? __expf(sc[j][1]) : 0.f;
            const float e2 = v0 ? __expf(sc[j][2]) : 0.f;
            const float e3 = v1 ? __expf(sc[j][3]) : 0.f;
            l0 += e0 + e1;
            l1 += e2 + e3;
            const unsigned h01 = h2pack(e0, e1);
            const unsigned h23 = h2pack(e2, e3);
            const int s2 = j >> 1;
            if ((j & 1) == 0) { pa[s2][0] = h01; pa[s2][1] = h23; }
            else              { pa[s2][2] = h01; pa[s2][3] = h23; }
        }

        #pragma unroll
        for (int s2 = 0; s2 < 4; s2++) {
            const int kcol = 16 * s2 + 2 * tg;
            #pragma unroll
            for (int j2 = 0; j2 < 16; j2++) {
                const unsigned b0 = *(const unsigned*)&vt[(8 * j2 + g) * VT_STR + kcol];
                const unsigned b1 = *(const unsigned*)&vt[(8 * j2 + g) * VT_STR + kcol + 8];
                mma16(o[j2], pa[s2][0], pa[s2][1], pa[s2][2], pa[s2][3], b0, b1);
            }
        }
        __syncthreads();
    }

    l0 += __shfl_xor_sync(0xffffffffu, l0, 1);
    l0 += __shfl_xor_sync(0xffffffffu, l0, 2);
    l1 += __shfl_xor_sync(0xffffffffu, l1, 1);
    l1 += __shfl_xor_sync(0xffffffffu, l1, 2);

    const bool  val0 = jr0 < cnt;
    const bool  val1 = jr1 < cnt;
    const float inv0 = 1.0f / l0;
    const float inv1 = 1.0f / l1;
    const int   h    = bh & 15;

    __half* ctx0 = g_Chc + ((size_t)(b * NN + jr0)) * ALLD + h * DD;
    __half* ctx1 = g_Chc + ((size_t)(b * NN + jr1)) * ALLD + h * DD;
    #pragma unroll
    for (int j2 = 0; j2 < 16; j2++) {
        const int ci = 8 * j2 + 2 * tg;
        if (val0) *(unsigned*)&ctx0[ci] = h2pack(o[j2][0] * inv0, o[j2][1] * inv0);
        if (val1) *(unsigned*)&ctx1[ci] = h2pack(o[j2][2] * inv1, o[j2][3] * inv1);
    }
}

// ---------------------------------------------------------------------------
// Kernel 5: output projection over compacted ctx rows; scatter via idx.
// grid (BB*64); block = 32 compacted rows; early exit.
// ---------------------------------------------------------------------------
#define GO_AS_STR 72
#define GO_AS_BYTES (32 * GO_AS_STR * 2)
#define GO_WS_BYTES (128 * GO_AS_STR * 2)
#define GO_SM_A(buf) ((buf) * (GO_AS_BYTES + GO_WS_BYTES))
#define GO_SM_W(buf) (GO_SM_A(buf) + GO_AS_BYTES)
#define GO_SMEM (2 * (GO_AS_BYTES + GO_WS_BYTES))

__global__ __launch_bounds__(128)
void gemm_out_kernel(const float* __restrict__ bo, float* __restrict__ out)
{
    extern __shared__ char sm[];

    const int b   = blockIdx.x >> 6;
    const int r0c = (blockIdx.x & 63) * 32;
    const int cnt = g_cnt[b];
    if (r0c >= cnt) return;

    const int t    = threadIdx.x;
    const int warp = t >> 5;
    const int lane = t & 31;
    const int g    = lane >> 2;
    const int tg   = lane & 3;

    const unsigned smu = (unsigned)__cvta_generic_to_shared(sm);
    const __half* A = g_Chc + (size_t)(b * NN + r0c) * ALLD;

    auto stage = [&](int kt, int buf) {
        const int k0 = kt * 64;
        const unsigned au = smu + GO_SM_A(buf);
        const unsigned wu = smu + GO_SM_W(buf);
        #pragma unroll
        for (int p = 0; p < 2; p++) {
            const int c   = t + p * 128;
            const int row = c >> 3;
            const int cd  = (c & 7) * 8;
            cp16(au + (row * GO_AS_STR + cd) * 2, A + (size_t)row * ALLD + k0 + cd);
        }
        #pragma unroll
        for (int p = 0; p < 8; p++) {
            const int c   = t + p * 128;
            const int row = c >> 3;
            const int cd  = (c & 7) * 8;
            cp16(wu + (row * GO_AS_STR + cd) * 2, g_Wot + (size_t)row * ALLD + k0 + cd);
        }
        asm volatile("cp.async.commit_group;" ::: "memory");
    };

    stage(0, 0);

    float acc[2][4][4];
    #pragma unroll
    for (int jm = 0; jm < 2; jm++)
        #pragma unroll
        for (int jn = 0; jn < 4; jn++) {
            acc[jm][jn][0]=0.f; acc[jm][jn][1]=0.f; acc[jm][jn][2]=0.f; acc[jm][jn][3]=0.f;
        }

    for (int kt = 0; kt < 32; kt++) {
        const int buf = kt & 1;
        asm volatile("cp.async.wait_group 0;" ::: "memory");
        __syncthreads();

        if (kt + 1 < 32) stage(kt + 1, buf ^ 1);

        const __half* as = (const __half*)(sm + GO_SM_A(buf));
        const __half* ws = (const __half*)(sm + GO_SM_W(buf));

        #pragma unroll
        for (int s = 0; s < 4; s++) {
            const int kc = 16 * s + 2 * tg;
            unsigned a[2][4];
            #pragma unroll
            for (int jm = 0; jm < 2; jm++) {
                a[jm][0] = *(const unsigned*)&as[(16 * jm + g)     * GO_AS_STR + kc];
                a[jm][1] = *(const unsigned*)&as[(16 * jm + g + 8) * GO_AS_STR + kc];
                a[jm][2] = *(const unsigned*)&as[(16 * jm + g)     * GO_AS_STR + kc + 8];
                a[jm][3] = *(const unsigned*)&as[(16 * jm + g + 8) * GO_AS_STR + kc + 8];
            }
            #pragma unroll
            for (int jn = 0; jn < 4; jn++) {
                const int n = 32 * warp + 8 * jn + g;
                const unsigned b0 = *(const unsigned*)&ws[n * GO_AS_STR + kc];
                const unsigned b1 = *(const unsigned*)&ws[n * GO_AS_STR + kc + 8];
                #pragma unroll
                for (int jm = 0; jm < 2; jm++)
                    mma16(acc[jm][jn], a[jm][0], a[jm][1], a[jm][2], a[jm][3], b0, b1);
            }
        }
        __syncthreads();
    }

    const int* idx = g_idx + b * NN;
    #pragma unroll
    for (int jm = 0; jm < 2; jm++) {
        const int jrow0 = r0c + 16 * jm + g;
        const int jrow1 = jrow0 + 8;
        const bool ok0 = jrow0 < cnt;
        const bool ok1 = jrow1 < cnt;
        const int orow0 = ok0 ? (b * NN + idx[jrow0]) : 0;
        const int orow1 = ok1 ? (b * NN + idx[jrow1]) : 0;
        #pragma unroll
        for (int jn = 0; jn < 4; jn++) {
            const int col = 32 * warp + 8 * jn + 2 * tg;
            const float bb0 = bo[col], bb1 = bo[col + 1];
            float2 w0, w1;
            w0.x = acc[jm][jn][0] + bb0;  w0.y = acc[jm][jn][1] + bb1;
            w1.x = acc[jm][jn][2] + bb0;  w1.y = acc[jm][jn][3] + bb1;
            if (ok0) *(float2*)&out[(size_t)orow0 * DD + col] = w0;
            if (ok1) *(float2*)&out[(size_t)orow1 * DD + col] = w1;
        }
    }
}

// ---------------------------------------------------------------------------
// Kernel 6: fill masked output rows with bias. grid 512, 256 thr.
// ---------------------------------------------------------------------------
__global__ __launch_bounds__(256)
void fill_out_kernel(const int* __restrict__ mask,
                     const float* __restrict__ bo,
                     float* __restrict__ out)
{
    const int i = blockIdx.x * 256 + threadIdx.x;
    const int total = BN * DD;
    for (int idx = i; idx < total; idx += gridDim.x * 256) {
        const int row = idx >> 7;
        if (mask[row] == 0)
            out[idx] = __ldg(&bo[idx & 127]);
    }
}

// ---------------------------------------------------------------------------
extern "C" void kernel_launch(void* const* d_in, const int* in_sizes, int n_in,
                              void* d_out, int out_size)
{
    const float* x    = (const float*)d_in[0];
    const int*   mask = (const int*)  d_in[1];
    const float* Wq   = (const float*)d_in[2];
    const float* bq   = (const float*)d_in[3];
    const float* Wk   = (const float*)d_in[4];
    const float* bk   = (const float*)d_in[5];
    const float* Wv   = (const float*)d_in[6];
    const float* bv   = (const float*)d_in[7];
    const float* Wo   = (const float*)d_in[8];
    const float* bo   = (const float*)d_in[9];
    float* out = (float*)d_out;

    compact_kernel<<<BB, 256>>>(mask);
    convert_kernel<<<(N_CVT + 255) / 256, 256>>>(x, Wq, Wk, Wv, Wo);

    cudaFuncSetAttribute((const void*)gemm_qkv_kernel,
                         cudaFuncAttributeMaxDynamicSharedMemorySize,
                         GQ_XS_BYTES + GQ_WS_BYTES);
    gemm_qkv_kernel<<<dim3(BB * 32, 48), 128, GQ_XS_BYTES + GQ_WS_BYTES>>>(bq, bk, bv);

    transpose_v_kernel<<<BB * HH * 32, 256>>>();

    cudaFuncSetAttribute((const void*)attn_fp16_kernel,
                         cudaFuncAttributeMaxDynamicSharedMemorySize, ATT_SMEM);
    attn_fp16_kernel<<<BB * HH * 32, 128, ATT_SMEM>>>();

    cudaFuncSetAttribute((const void*)gemm_out_kernel,
                         cudaFuncAttributeMaxDynamicSharedMemorySize, GO_SMEM);
    gemm_out_kernel<<<BB * 64, 128, GO_SMEM>>>(bo, out);

    fill_out_kernel<<<512, 256>>>(mask, bo, out);
}

// round 14
// speedup vs baseline: 3.2497x; 1.0803x over previous
#include <cuda_runtime.h>
#include <cuda_fp16.h>
#include <math.h>

#define BB 2
#define NN 2048
#define DD 128
#define HH 16
#define ALLD 2048
#define BN  4096

#define BQ 64          // q rows per attention block (4 warps x 16)
#define TK 64          // keys per tile

#define KS_STR 136     // halves per K row
#define VT_STR 72      // halves per V^T row

// Scratch (zero-initialized device globals; tails beyond cnt are never
// written and therefore stay zero — guarded stores keep it that way)
__device__ __half g_xc [BN*DD];         // compacted x as half [b][j][d]
__device__ __half g_Wt [3*ALLD*DD];     // W{q,k,v}^T half [n][k], SC in Wq
__device__ __half g_Wot[DD*ALLD];       // Wo^T half [n][k]
__device__ __half g_Qc [BB*HH*NN*DD];   // compacted Q [bh][j][d], pre-scaled
__device__ __half g_Kc [BB*HH*NN*DD];   // compacted K [bh][j][d]
__device__ __half g_Vtc[BB*HH*DD*NN];   // compacted V^T [bh][d][j]
__device__ __half g_Chc[BB*NN*ALLD];    // compacted ctx [b][j][ALLD]
__device__ int    g_idx[BB*NN];         // valid-token indices
__device__ int    g_cnt[BB];

__device__ __forceinline__ unsigned h2pack(float x, float y) {
    __half2 h = __floats2half2_rn(x, y);
    return *(unsigned*)&h;
}

__device__ __forceinline__ void mma16(float* c,
                                      unsigned a0, unsigned a1, unsigned a2, unsigned a3,
                                      unsigned b0, unsigned b1) {
    asm volatile(
        "mma.sync.aligned.m16n8k16.row.col.f32.f16.f16.f32 "
        "{%0,%1,%2,%3}, {%4,%5,%6,%7}, {%8,%9}, {%0,%1,%2,%3};"
        : "+f"(c[0]), "+f"(c[1]), "+f"(c[2]), "+f"(c[3])
        : "r"(a0), "r"(a1), "r"(a2), "r"(a3), "r"(b0), "r"(b1));
}

__device__ __forceinline__ void cp16(unsigned dst, const void* src) {
    asm volatile("cp.async.cg.shared.global [%0], [%1], 16;" :: "r"(dst), "l"(src));
}

#define SCQ 0.08838834764831845f   // 1/sqrt(128)

// ---------------------------------------------------------------------------
// Kernel 0: compact valid token indices per batch. grid BB, 256 threads.
// ---------------------------------------------------------------------------
__global__ __launch_bounds__(256)
void compact_kernel(const int* __restrict__ mask)
{
    __shared__ int cnts[256];
    __shared__ int offs[256];

    const int b = blockIdx.x;
    const int t = threadIdx.x;
    const int base = t * 8;

    int mloc[8];
    int c = 0;
    #pragma unroll
    for (int i = 0; i < 8; i++) {
        mloc[i] = mask[b * NN + base + i];
        c += (mloc[i] != 0);
    }
    cnts[t] = c;
    __syncthreads();

    if (t == 0) {
        int run = 0;
        for (int i = 0; i < 256; i++) { offs[i] = run; run += cnts[i]; }
        g_cnt[b] = run;
    }
    __syncthreads();

    int o = offs[t];
    #pragma unroll
    for (int i = 0; i < 8; i++)
        if (mloc[i]) g_idx[b * NN + (o++)] = base + i;

    __syncthreads();
    const int cnt = g_cnt[b];
    for (int i = cnt + t; i < NN; i += 256) g_idx[b * NN + i] = 0;
}

// ---------------------------------------------------------------------------
// Kernel 1: convert weights to half; gather x into compacted xc (half).
// ---------------------------------------------------------------------------
#define N_XH  (BN*DD)
#define N_WT  (3*ALLD*DD)
#define N_WOT (DD*ALLD)
#define N_CVT (N_XH + N_WT + N_WOT)

__global__ __launch_bounds__(256)
void convert_kernel(const float* __restrict__ x,
                    const float* __restrict__ Wq,
                    const float* __restrict__ Wk,
                    const float* __restrict__ Wv,
                    const float* __restrict__ Wo)
{
    const int idx = blockIdx.x * 256 + threadIdx.x;
    if (idx < N_XH) {
        const int r = idx >> 7;
        const int d = idx & 127;
        const int b = r >> 11;
        const int j = r & 2047;
        if (j < g_cnt[b])
            g_xc[idx] = __float2half_rn(
                x[((size_t)(b * NN + g_idx[b * NN + j])) * DD + d]);
    } else if (idx < N_XH + N_WT) {
        const int i = idx - N_XH;
        const int r = i >> 7;
        const int k = i & 127;
        const int proj = r >> 11;
        const int c    = r & 2047;
        const float v = (proj == 0) ? Wq[k * ALLD + c] * SCQ
                      : (proj == 1) ? Wk[k * ALLD + c]
                                    : Wv[k * ALLD + c];
        g_Wt[i] = __float2half_rn(v);
    } else if (idx < N_CVT) {
        const int i = idx - N_XH - N_WT;
        const int n = i >> 11;
        const int k = i & 2047;
        g_Wot[i] = __float2half_rn(Wo[k * DD + n]);
    }
}

// ---------------------------------------------------------------------------
// Kernel 2: QKV projection over compacted rows (fp16 MMA).
// grid (BB*32, 48); block = 64 compacted rows x 128 cols; early exit.
// V output (proj==2) is transposed in-block and written to g_Vtc directly.
// ---------------------------------------------------------------------------
#define GQ_XS_STR 136
#define GQ_XS_BYTES (64 * GQ_XS_STR * 2)
#define GQ_WS_BYTES (128 * GQ_XS_STR * 2)

__global__ __launch_bounds__(128)
void gemm_qkv_kernel(const float* __restrict__ bq,
                     const float* __restrict__ bk,
                     const float* __restrict__ bv)
{
    extern __shared__ char sm[];
    __half* xs = (__half*)sm;
    __half* ws = (__half*)(sm + GQ_XS_BYTES);

    const int b  = blockIdx.x >> 5;
    const int j0 = (blockIdx.x & 31) * 64;
    const int cnt = g_cnt[b];
    if (j0 >= cnt) return;

    const int n0 = blockIdx.y * 128;
    const int proj = n0 >> 11;
    const int h    = (n0 >> 7) & 15;

    const int t    = threadIdx.x;
    const int warp = t >> 5;
    const int lane = t & 31;
    const int g    = lane >> 2;
    const int tg   = lane & 3;
    const int m0   = warp * 16;

    const unsigned smu = (unsigned)__cvta_generic_to_shared(sm);

    #pragma unroll
    for (int p = 0; p < 8; p++) {
        const int c   = t + p * 128;
        const int row = c >> 4;
        const int cd  = (c & 15) * 8;
        cp16(smu + (row * GQ_XS_STR + cd) * 2,
             g_xc + ((size_t)(b * NN + j0 + row)) * DD + cd);
    }
    #pragma unroll
    for (int p = 0; p < 16; p++) {
        const int c   = t + p * 128;
        const int row = c >> 4;
        const int cd  = (c & 15) * 8;
        cp16(smu + GQ_XS_BYTES + (row * GQ_XS_STR + cd) * 2,
             g_Wt + (size_t)(n0 + row) * DD + cd);
    }
    asm volatile("cp.async.commit_group;" ::: "memory");
    asm volatile("cp.async.wait_group 0;" ::: "memory");
    __syncthreads();

    float acc[16][4];
    #pragma unroll
    for (int j = 0; j < 16; j++) { acc[j][0]=0.f; acc[j][1]=0.f; acc[j][2]=0.f; acc[j][3]=0.f; }

    #pragma unroll
    for (int s = 0; s < 8; s++) {
        const int kc = 16 * s + 2 * tg;
        const unsigned a0 = *(const unsigned*)&xs[(m0 + g)     * GQ_XS_STR + kc];
        const unsigned a1 = *(const unsigned*)&xs[(m0 + g + 8) * GQ_XS_STR + kc];
        const unsigned a2 = *(const unsigned*)&xs[(m0 + g)     * GQ_XS_STR + kc + 8];
        const unsigned a3 = *(const unsigned*)&xs[(m0 + g + 8) * GQ_XS_STR + kc + 8];
        #pragma unroll
        for (int j = 0; j < 16; j++) {
            const unsigned b0 = *(const unsigned*)&ws[(8 * j + g) * GQ_XS_STR + kc];
            const unsigned b1 = *(const unsigned*)&ws[(8 * j + g) * GQ_XS_STR + kc + 8];
            mma16(acc[j], a0, a1, a2, a3, b0, b1);
        }
    }

    const float* bias = (proj == 0) ? bq : (proj == 1) ? bk : bv;
    const int bcol = n0 & 2047;
    const int row0 = j0 + m0 + g;        // local compacted row
    const int row1 = row0 + 8;
    const int bh   = b * HH + h;

    if (proj < 2) {
        const float bscl = (proj == 0) ? SCQ : 1.0f;
        __half* dst = (proj == 0) ? g_Qc : g_Kc;
        __half* d0 = dst + ((size_t)bh * NN + row0) * DD;
        __half* d1 = dst + ((size_t)bh * NN + row1) * DD;
        const bool s0ok = row0 < cnt;
        const bool s1ok = row1 < cnt;

        #pragma unroll
        for (int j = 0; j < 16; j++) {
            const int ci = 8 * j + 2 * tg;
            const float bb0 = bias[bcol + ci]     * bscl;
            const float bb1 = bias[bcol + ci + 1] * bscl;
            if (s0ok) *(unsigned*)&d0[ci] = h2pack(acc[j][0] + bb0, acc[j][1] + bb1);
            if (s1ok) *(unsigned*)&d1[ci] = h2pack(acc[j][2] + bb0, acc[j][3] + bb1);
        }
    } else {
        // V: transpose in smem (reuse staging buffer), write Vtc directly.
        // Tail rows (>= cnt) come from zero xc -> acc = bias (finite); the
        // attention PV multiplies them by P==0, so unguarded writes are safe.
        __syncthreads();                  // all MMA smem reads complete
        __half* ts = (__half*)sm;         // [128 d][72] (stride 144B, 16B-aligned)
        const int lr0 = m0 + g;           // local row within 64-tile
        const int lr1 = lr0 + 8;
        #pragma unroll
        for (int j = 0; j < 16; j++) {
            const int ci = 8 * j + 2 * tg;
            const float bb0 = bias[bcol + ci];
            const float bb1 = bias[bcol + ci + 1];
            ts[(ci    ) * VT_STR + lr0] = __float2half_rn(acc[j][0] + bb0);
            ts[(ci + 1) * VT_STR + lr0] = __float2half_rn(acc[j][1] + bb1);
            ts[(ci    ) * VT_STR + lr1] = __float2half_rn(acc[j][2] + bb0);
            ts[(ci + 1) * VT_STR + lr1] = __float2half_rn(acc[j][3] + bb1);
        }
        __syncthreads();

        const int d = t;                  // 0..127
        __half* dst = g_Vtc + ((size_t)bh * DD + d) * NN + j0;
        #pragma unroll
        for (int p = 0; p < 8; p++)
            *(uint4*)&dst[p * 8] = *(const uint4*)&ts[d * VT_STR + p * 8];
    }
}

// ---------------------------------------------------------------------------
// Kernel 4: flash attention over compacted q/k/v.
// ---------------------------------------------------------------------------
#define KS_BYTES (TK * KS_STR * 2)
#define VT_BYTES (DD * VT_STR * 2)
#define SM_KS(buf)  ((buf) * KS_BYTES)
#define SM_VT(buf)  (2 * KS_BYTES + (buf) * VT_BYTES)
#define ATT_SMEM    (2 * KS_BYTES + 2 * VT_BYTES)

__global__ __launch_bounds__(128)
void attn_fp16_kernel()
{
    extern __shared__ char sm[];

    const int bid = blockIdx.x;
    const int qt  = bid & 31;
    const int bh  = bid >> 5;
    const int b   = bh >> 4;
    const int n0  = qt * BQ;

    const int cnt = g_cnt[b];
    if (n0 >= cnt) return;

    const int t    = threadIdx.x;
    const int warp = t >> 5;
    const int lane = t & 31;
    const int g    = lane >> 2;
    const int tg   = lane & 3;
    const int m0   = warp * 16;

    const __half* Qc  = g_Qc  + (size_t)bh * NN * DD;
    const __half* Kc  = g_Kc  + (size_t)bh * NN * DD;
    const __half* Vtc = g_Vtc + (size_t)bh * DD * NN;

    const unsigned smu = (unsigned)__cvta_generic_to_shared(sm);

    auto stage = [&](int kt, int buf) {
        const int k0 = kt * TK;
        const unsigned ksu = smu + SM_KS(buf);
        const unsigned vtu = smu + SM_VT(buf);
        #pragma unroll
        for (int p = 0; p < 8; p++) {
            const int c   = t + p * 128;
            const int row = c >> 4;
            const int cd  = (c & 15) * 8;
            cp16(ksu + (row * KS_STR + cd) * 2, Kc + (size_t)(k0 + row) * DD + cd);
        }
        #pragma unroll
        for (int p = 0; p < 8; p++) {
            const int c   = t + p * 128;
            const int row = c >> 3;
            const int cd  = (c & 7) * 8;
            cp16(vtu + (row * VT_STR + cd) * 2, Vtc + (size_t)row * NN + k0 + cd);
        }
        asm volatile("cp.async.commit_group;" ::: "memory");
    };

    // ---- Q fragments: direct compacted rows ----
    const int jr0 = n0 + m0 + g;
    const int jr1 = jr0 + 8;
    unsigned qa[8][4];
    {
        const __half* q0 = Qc + (size_t)jr0 * DD;
        const __half* q1 = Qc + (size_t)jr1 * DD;
        #pragma unroll
        for (int s = 0; s < 8; s++) {
            const int c = 16 * s + 2 * tg;
            qa[s][0] = *(const unsigned*)&q0[c];
            qa[s][1] = *(const unsigned*)&q1[c];
            qa[s][2] = *(const unsigned*)&q0[c + 8];
            qa[s][3] = *(const unsigned*)&q1[c + 8];
        }
    }

    const int NTc = (cnt + TK - 1) / TK;
    stage(0, 0);

    float o[16][4];
    #pragma unroll
    for (int j = 0; j < 16; j++) { o[j][0]=0.f; o[j][1]=0.f; o[j][2]=0.f; o[j][3]=0.f; }
    float l0 = 0.f, l1 = 0.f;

    for (int kt = 0; kt < NTc; kt++) {
        const int buf = kt & 1;
        const int k0  = kt * TK;
        asm volatile("cp.async.wait_group 0;" ::: "memory");
        __syncthreads();

        if (kt + 1 < NTc) stage(kt + 1, buf ^ 1);

        const __half* ks = (const __half*)(sm + SM_KS(buf));
        const __half* vt = (const __half*)(sm + SM_VT(buf));

        float sc[8][4];
        #pragma unroll
        for (int j = 0; j < 8; j++) { sc[j][0]=0.f; sc[j][1]=0.f; sc[j][2]=0.f; sc[j][3]=0.f; }

        #pragma unroll
        for (int s = 0; s < 8; s++) {
            const int dcol = 16 * s + 2 * tg;
            #pragma unroll
            for (int j = 0; j < 8; j++) {
                const unsigned b0 = *(const unsigned*)&ks[(8 * j + g) * KS_STR + dcol];
                const unsigned b1 = *(const unsigned*)&ks[(8 * j + g) * KS_STR + dcol + 8];
                mma16(sc[j], qa[s][0], qa[s][1], qa[s][2], qa[s][3], b0, b1);
            }
        }

        // ---- softmax; key validity = positional (compacted) ----
        unsigned pa[4][4];
        #pragma unroll
        for (int j = 0; j < 8; j++) {
            const int ci = 8 * j + 2 * tg;
            const bool v0 = (k0 + ci)     < cnt;
            const bool v1 = (k0 + ci + 1) < cnt;
            const float e0 = v0 ? __expf(sc[j][0]) : 0.f;
            const float e1 = v1 ? __expf(sc[j][1]) : 0.f;
            const float e2 = v0 ? __expf(sc[j][2]) : 0.f;
            const float e3 = v1 ? __expf(sc[j][3]) : 0.f;
            l0 += e0 + e1;
            l1 += e2 + e3;
            const unsigned h01 = h2pack(e0, e1);
            const unsigned h23 = h2pack(e2, e3);
            const int s2 = j >> 1;
            if ((j & 1) == 0) { pa[s2][0] = h01; pa[s2][1] = h23; }
            else              { pa[s2][2] = h01; pa[s2][3] = h23; }
        }

        #pragma unroll
        for (int s2 = 0; s2 < 4; s2++) {
            const int kcol = 16 * s2 + 2 * tg;
            #pragma unroll
            for (int j2 = 0; j2 < 16; j2++) {
                const unsigned b0 = *(const unsigned*)&vt[(8 * j2 + g) * VT_STR + kcol];
                const unsigned b1 = *(const unsigned*)&vt[(8 * j2 + g) * VT_STR + kcol + 8];
                mma16(o[j2], pa[s2][0], pa[s2][1], pa[s2][2], pa[s2][3], b0, b1);
            }
        }
        __syncthreads();
    }

    l0 += __shfl_xor_sync(0xffffffffu, l0, 1);
    l0 += __shfl_xor_sync(0xffffffffu, l0, 2);
    l1 += __shfl_xor_sync(0xffffffffu, l1, 1);
    l1 += __shfl_xor_sync(0xffffffffu, l1, 2);

    const bool  val0 = jr0 < cnt;
    const bool  val1 = jr1 < cnt;
    const float inv0 = 1.0f / l0;
    const float inv1 = 1.0f / l1;
    const int   h    = bh & 15;

    __half* ctx0 = g_Chc + ((size_t)(b * NN + jr0)) * ALLD + h * DD;
    __half* ctx1 = g_Chc + ((size_t)(b * NN + jr1)) * ALLD + h * DD;
    #pragma unroll
    for (int j2 = 0; j2 < 16; j2++) {
        const int ci = 8 * j2 + 2 * tg;
        if (val0) *(unsigned*)&ctx0[ci] = h2pack(o[j2][0] * inv0, o[j2][1] * inv0);
        if (val1) *(unsigned*)&ctx1[ci] = h2pack(o[j2][2] * inv1, o[j2][3] * inv1);
    }
}

// ---------------------------------------------------------------------------
// Kernel 5: output projection over compacted ctx rows; scatter via idx.
// ---------------------------------------------------------------------------
#define GO_AS_STR 72
#define GO_AS_BYTES (32 * GO_AS_STR * 2)
#define GO_WS_BYTES (128 * GO_AS_STR * 2)
#define GO_SM_A(buf) ((buf) * (GO_AS_BYTES + GO_WS_BYTES))
#define GO_SM_W(buf) (GO_SM_A(buf) + GO_AS_BYTES)
#define GO_SMEM (2 * (GO_AS_BYTES + GO_WS_BYTES))

__global__ __launch_bounds__(128)
void gemm_out_kernel(const float* __restrict__ bo, float* __restrict__ out)
{
    extern __shared__ char sm[];

    const int b   = blockIdx.x >> 6;
    const int r0c = (blockIdx.x & 63) * 32;
    const int cnt = g_cnt[b];
    if (r0c >= cnt) return;

    const int t    = threadIdx.x;
    const int warp = t >> 5;
    const int lane = t & 31;
    const int g    = lane >> 2;
    const int tg   = lane & 3;

    const unsigned smu = (unsigned)__cvta_generic_to_shared(sm);
    const __half* A = g_Chc + (size_t)(b * NN + r0c) * ALLD;

    auto stage = [&](int kt, int buf) {
        const int k0 = kt * 64;
        const unsigned au = smu + GO_SM_A(buf);
        const unsigned wu = smu + GO_SM_W(buf);
        #pragma unroll
        for (int p = 0; p < 2; p++) {
            const int c   = t + p * 128;
            const int row = c >> 3;
            const int cd  = (c & 7) * 8;
            cp16(au + (row * GO_AS_STR + cd) * 2, A + (size_t)row * ALLD + k0 + cd);
        }
        #pragma unroll
        for (int p = 0; p < 8; p++) {
            const int c   = t + p * 128;
            const int row = c >> 3;
            const int cd  = (c & 7) * 8;
            cp16(wu + (row * GO_AS_STR + cd) * 2, g_Wot + (size_t)row * ALLD + k0 + cd);
        }
        asm volatile("cp.async.commit_group;" ::: "memory");
    };

    stage(0, 0);

    float acc[2][4][4];
    #pragma unroll
    for (int jm = 0; jm < 2; jm++)
        #pragma unroll
        for (int jn = 0; jn < 4; jn++) {
            acc[jm][jn][0]=0.f; acc[jm][jn][1]=0.f; acc[jm][jn][2]=0.f; acc[jm][jn][3]=0.f;
        }

    for (int kt = 0; kt < 32; kt++) {
        const int buf = kt & 1;
        asm volatile("cp.async.wait_group 0;" ::: "memory");
        __syncthreads();

        if (kt + 1 < 32) stage(kt + 1, buf ^ 1);

        const __half* as = (const __half*)(sm + GO_SM_A(buf));
        const __half* ws = (const __half*)(sm + GO_SM_W(buf));

        #pragma unroll
        for (int s = 0; s < 4; s++) {
            const int kc = 16 * s + 2 * tg;
            unsigned a[2][4];
            #pragma unroll
            for (int jm = 0; jm < 2; jm++) {
                a[jm][0] = *(const unsigned*)&as[(16 * jm + g)     * GO_AS_STR + kc];
                a[jm][1] = *(const unsigned*)&as[(16 * jm + g + 8) * GO_AS_STR + kc];
                a[jm][2] = *(const unsigned*)&as[(16 * jm + g)     * GO_AS_STR + kc + 8];
                a[jm][3] = *(const unsigned*)&as[(16 * jm + g + 8) * GO_AS_STR + kc + 8];
            }
            #pragma unroll
            for (int jn = 0; jn < 4; jn++) {
                const int n = 32 * warp + 8 * jn + g;
                const unsigned b0 = *(const unsigned*)&ws[n * GO_AS_STR + kc];
                const unsigned b1 = *(const unsigned*)&ws[n * GO_AS_STR + kc + 8];
                #pragma unroll
                for (int jm = 0; jm < 2; jm++)
                    mma16(acc[jm][jn], a[jm][0], a[jm][1], a[jm][2], a[jm][3], b0, b1);
            }
        }
        __syncthreads();
    }

    const int* idx = g_idx + b * NN;
    #pragma unroll
    for (int jm = 0; jm < 2; jm++) {
        const int jrow0 = r0c + 16 * jm + g;
        const int jrow1 = jrow0 + 8;
        const bool ok0 = jrow0 < cnt;
        const bool ok1 = jrow1 < cnt;
        const int orow0 = ok0 ? (b * NN + idx[jrow0]) : 0;
        const int orow1 = ok1 ? (b * NN + idx[jrow1]) : 0;
        #pragma unroll
        for (int jn = 0; jn < 4; jn++) {
            const int col = 32 * warp + 8 * jn + 2 * tg;
            const float bb0 = bo[col], bb1 = bo[col + 1];
            float2 w0, w1;
            w0.x = acc[jm][jn][0] + bb0;  w0.y = acc[jm][jn][1] + bb1;
            w1.x = acc[jm][jn][2] + bb0;  w1.y = acc[jm][jn][3] + bb1;
            if (ok0) *(float2*)&out[(size_t)orow0 * DD + col] = w0;
            if (ok1) *(float2*)&out[(size_t)orow1 * DD + col] = w1;
        }
    }
}

// ---------------------------------------------------------------------------
// Kernel 6: fill masked output rows with bias. grid 512, 256 thr.
// ---------------------------------------------------------------------------
__global__ __launch_bounds__(256)
void fill_out_kernel(const int* __restrict__ mask,
                     const float* __restrict__ bo,
                     float* __restrict__ out)
{
    const int i = blockIdx.x * 256 + threadIdx.x;
    const int total = BN * DD;
    for (int idx = i; idx < total; idx += gridDim.x * 256) {
        const int row = idx >> 7;
        if (mask[row] == 0)
            out[idx] = __ldg(&bo[idx & 127]);
    }
}

// ---------------------------------------------------------------------------
extern "C" void kernel_launch(void* const* d_in, const int* in_sizes, int n_in,
                              void* d_out, int out_size)
{
    const float* x    = (const float*)d_in[0];
    const int*   mask = (const int*)  d_in[1];
    const float* Wq   = (const float*)d_in[2];
    const float* bq   = (const float*)d_in[3];
    const float* Wk   = (const float*)d_in[4];
    const float* bk   = (const float*)d_in[5];
    const float* Wv   = (const float*)d_in[6];
    const float* bv   = (const float*)d_in[7];
    const float* Wo   = (const float*)d_in[8];
    const float* bo   = (const float*)d_in[9];
    float* out = (float*)d_out;

    compact_kernel<<<BB, 256>>>(mask);
    convert_kernel<<<(N_CVT + 255) / 256, 256>>>(x, Wq, Wk, Wv, Wo);

    cudaFuncSetAttribute((const void*)gemm_qkv_kernel,
                         cudaFuncAttributeMaxDynamicSharedMemorySize,
                         GQ_XS_BYTES + GQ_WS_BYTES);
    gemm_qkv_kernel<<<dim3(BB * 32, 48), 128, GQ_XS_BYTES + GQ_WS_BYTES>>>(bq, bk, bv);

    cudaFuncSetAttribute((const void*)attn_fp16_kernel,
                         cudaFuncAttributeMaxDynamicSharedMemorySize, ATT_SMEM);
    attn_fp16_kernel<<<BB * HH * 32, 128, ATT_SMEM>>>();

    cudaFuncSetAttribute((const void*)gemm_out_kernel,
                         cudaFuncAttributeMaxDynamicSharedMemorySize, GO_SMEM);
    gemm_out_kernel<<<BB * 64, 128, GO_SMEM>>>(bo, out);

    fill_out_kernel<<<512, 256>>>(mask, bo, out);
}

// round 15
// speedup vs baseline: 3.3199x; 1.0216x over previous
#include <cuda_runtime.h>
#include <cuda_fp16.h>
#include <math.h>

#define BB 2
#define NN 2048
#define DD 128
#define HH 16
#define ALLD 2048
#define BN  4096

#define BQ 64          // q rows per attention block (4 warps x 16)
#define TK 64          // keys per tile

#define KS_STR 136     // halves per K row
#define VT_STR 72      // halves per V^T row

// Scratch (zero-initialized device globals; tails beyond cnt are never
// written and therefore stay zero — guarded stores keep it that way)
__device__ __half g_xc [BN*DD];         // compacted x as half [b][j][d]
__device__ __half g_Wt [3*ALLD*DD];     // W{q,k,v}^T half [n][k], SC in Wq
__device__ __half g_Wot[DD*ALLD];       // Wo^T half [n][k]
__device__ __half g_Qc [BB*HH*NN*DD];   // compacted Q [bh][j][d], pre-scaled
__device__ __half g_Kc [BB*HH*NN*DD];   // compacted K [bh][j][d]
__device__ __half g_Vtc[BB*HH*DD*NN];   // compacted V^T [bh][d][j]
__device__ __half g_Chc[BB*NN*ALLD];    // compacted ctx [b][j][ALLD]
__device__ int    g_idx[BB*NN];         // valid-token indices
__device__ int    g_cnt[BB];

__device__ __forceinline__ unsigned h2pack(float x, float y) {
    __half2 h = __floats2half2_rn(x, y);
    return *(unsigned*)&h;
}

__device__ __forceinline__ void mma16(float* c,
                                      unsigned a0, unsigned a1, unsigned a2, unsigned a3,
                                      unsigned b0, unsigned b1) {
    asm volatile(
        "mma.sync.aligned.m16n8k16.row.col.f32.f16.f16.f32 "
        "{%0,%1,%2,%3}, {%4,%5,%6,%7}, {%8,%9}, {%0,%1,%2,%3};"
        : "+f"(c[0]), "+f"(c[1]), "+f"(c[2]), "+f"(c[3])
        : "r"(a0), "r"(a1), "r"(a2), "r"(a3), "r"(b0), "r"(b1));
}

__device__ __forceinline__ void cp16(unsigned dst, const void* src) {
    asm volatile("cp.async.cg.shared.global [%0], [%1], 16;" :: "r"(dst), "l"(src));
}

#define SCQ 0.08838834764831845f   // 1/sqrt(128)

// ---------------------------------------------------------------------------
// Kernel 0: compact valid token indices per batch. grid BB, 256 threads.
// ---------------------------------------------------------------------------
__global__ __launch_bounds__(256)
void compact_kernel(const int* __restrict__ mask)
{
    __shared__ int cnts[256];
    __shared__ int offs[256];

    const int b = blockIdx.x;
    const int t = threadIdx.x;
    const int base = t * 8;

    int mloc[8];
    int c = 0;
    #pragma unroll
    for (int i = 0; i < 8; i++) {
        mloc[i] = mask[b * NN + base + i];
        c += (mloc[i] != 0);
    }
    cnts[t] = c;
    __syncthreads();

    if (t == 0) {
        int run = 0;
        for (int i = 0; i < 256; i++) { offs[i] = run; run += cnts[i]; }
        g_cnt[b] = run;
    }
    __syncthreads();

    int o = offs[t];
    #pragma unroll
    for (int i = 0; i < 8; i++)
        if (mloc[i]) g_idx[b * NN + (o++)] = base + i;

    __syncthreads();
    const int cnt = g_cnt[b];
    for (int i = cnt + t; i < NN; i += 256) g_idx[b * NN + i] = 0;
}

// ---------------------------------------------------------------------------
// Kernel 1: convert weights to half; gather x into compacted xc (half).
// ---------------------------------------------------------------------------
#define N_XH  (BN*DD)
#define N_WT  (3*ALLD*DD)
#define N_WOT (DD*ALLD)
#define N_CVT (N_XH + N_WT + N_WOT)

__global__ __launch_bounds__(256)
void convert_kernel(const float* __restrict__ x,
                    const float* __restrict__ Wq,
                    const float* __restrict__ Wk,
                    const float* __restrict__ Wv,
                    const float* __restrict__ Wo)
{
    const int idx = blockIdx.x * 256 + threadIdx.x;
    if (idx < N_XH) {
        const int r = idx >> 7;
        const int d = idx & 127;
        const int b = r >> 11;
        const int j = r & 2047;
        if (j < g_cnt[b])
            g_xc[idx] = __float2half_rn(
                x[((size_t)(b * NN + g_idx[b * NN + j])) * DD + d]);
    } else if (idx < N_XH + N_WT) {
        const int i = idx - N_XH;
        const int r = i >> 7;
        const int k = i & 127;
        const int proj = r >> 11;
        const int c    = r & 2047;
        const float v = (proj == 0) ? Wq[k * ALLD + c] * SCQ
                      : (proj == 1) ? Wk[k * ALLD + c]
                                    : Wv[k * ALLD + c];
        g_Wt[i] = __float2half_rn(v);
    } else if (idx < N_CVT) {
        const int i = idx - N_XH - N_WT;
        const int n = i >> 11;
        const int k = i & 2047;
        g_Wot[i] = __float2half_rn(Wo[k * DD + n]);
    }
}

// ---------------------------------------------------------------------------
// Kernel 2: QKV projection over compacted rows (fp16 MMA).
// grid (BB*32, 48); block = 64 compacted rows x 128 cols; early exit.
// V output (proj==2) is transposed in-block and written to g_Vtc directly.
// ---------------------------------------------------------------------------
#define GQ_XS_STR 136
#define GQ_XS_BYTES (64 * GQ_XS_STR * 2)
#define GQ_WS_BYTES (128 * GQ_XS_STR * 2)

__global__ __launch_bounds__(128)
void gemm_qkv_kernel(const float* __restrict__ bq,
                     const float* __restrict__ bk,
                     const float* __restrict__ bv)
{
    extern __shared__ char sm[];
    __half* xs = (__half*)sm;
    __half* ws = (__half*)(sm + GQ_XS_BYTES);

    const int b  = blockIdx.x >> 5;
    const int j0 = (blockIdx.x & 31) * 64;
    const int cnt = g_cnt[b];
    if (j0 >= cnt) return;

    const int n0 = blockIdx.y * 128;
    const int proj = n0 >> 11;
    const int h    = (n0 >> 7) & 15;

    const int t    = threadIdx.x;
    const int warp = t >> 5;
    const int lane = t & 31;
    const int g    = lane >> 2;
    const int tg   = lane & 3;
    const int m0   = warp * 16;

    const unsigned smu = (unsigned)__cvta_generic_to_shared(sm);

    #pragma unroll
    for (int p = 0; p < 8; p++) {
        const int c   = t + p * 128;
        const int row = c >> 4;
        const int cd  = (c & 15) * 8;
        cp16(smu + (row * GQ_XS_STR + cd) * 2,
             g_xc + ((size_t)(b * NN + j0 + row)) * DD + cd);
    }
    #pragma unroll
    for (int p = 0; p < 16; p++) {
        const int c   = t + p * 128;
        const int row = c >> 4;
        const int cd  = (c & 15) * 8;
        cp16(smu + GQ_XS_BYTES + (row * GQ_XS_STR + cd) * 2,
             g_Wt + (size_t)(n0 + row) * DD + cd);
    }
    asm volatile("cp.async.commit_group;" ::: "memory");
    asm volatile("cp.async.wait_group 0;" ::: "memory");
    __syncthreads();

    float acc[16][4];
    #pragma unroll
    for (int j = 0; j < 16; j++) { acc[j][0]=0.f; acc[j][1]=0.f; acc[j][2]=0.f; acc[j][3]=0.f; }

    #pragma unroll
    for (int s = 0; s < 8; s++) {
        const int kc = 16 * s + 2 * tg;
        const unsigned a0 = *(const unsigned*)&xs[(m0 + g)     * GQ_XS_STR + kc];
        const unsigned a1 = *(const unsigned*)&xs[(m0 + g + 8) * GQ_XS_STR + kc];
        const unsigned a2 = *(const unsigned*)&xs[(m0 + g)     * GQ_XS_STR + kc + 8];
        const unsigned a3 = *(const unsigned*)&xs[(m0 + g + 8) * GQ_XS_STR + kc + 8];
        #pragma unroll
        for (int j = 0; j < 16; j++) {
            const unsigned b0 = *(const unsigned*)&ws[(8 * j + g) * GQ_XS_STR + kc];
            const unsigned b1 = *(const unsigned*)&ws[(8 * j + g) * GQ_XS_STR + kc + 8];
            mma16(acc[j], a0, a1, a2, a3, b0, b1);
        }
    }

    const float* bias = (proj == 0) ? bq : (proj == 1) ? bk : bv;
    const int bcol = n0 & 2047;
    const int row0 = j0 + m0 + g;        // local compacted row
    const int row1 = row0 + 8;
    const int bh   = b * HH + h;

    if (proj < 2) {
        const float bscl = (proj == 0) ? SCQ : 1.0f;
        __half* dst = (proj == 0) ? g_Qc : g_Kc;
        __half* d0 = dst + ((size_t)bh * NN + row0) * DD;
        __half* d1 = dst + ((size_t)bh * NN + row1) * DD;
        const bool s0ok = row0 < cnt;
        const bool s1ok = row1 < cnt;

        #pragma unroll
        for (int j = 0; j < 16; j++) {
            const int ci = 8 * j + 2 * tg;
            const float bb0 = bias[bcol + ci]     * bscl;
            const float bb1 = bias[bcol + ci + 1] * bscl;
            if (s0ok) *(unsigned*)&d0[ci] = h2pack(acc[j][0] + bb0, acc[j][1] + bb1);
            if (s1ok) *(unsigned*)&d1[ci] = h2pack(acc[j][2] + bb0, acc[j][3] + bb1);
        }
    } else {
        // V: transpose in smem (reuse staging buffer), write Vtc directly.
        __syncthreads();                  // all MMA smem reads complete
        __half* ts = (__half*)sm;         // [128 d][72]
        const int lr0 = m0 + g;
        const int lr1 = lr0 + 8;
        #pragma unroll
        for (int j = 0; j < 16; j++) {
            const int ci = 8 * j + 2 * tg;
            const float bb0 = bias[bcol + ci];
            const float bb1 = bias[bcol + ci + 1];
            ts[(ci    ) * VT_STR + lr0] = __float2half_rn(acc[j][0] + bb0);
            ts[(ci + 1) * VT_STR + lr0] = __float2half_rn(acc[j][1] + bb1);
            ts[(ci    ) * VT_STR + lr1] = __float2half_rn(acc[j][2] + bb0);
            ts[(ci + 1) * VT_STR + lr1] = __float2half_rn(acc[j][3] + bb1);
        }
        __syncthreads();

        const int d = t;                  // 0..127
        __half* dst = g_Vtc + ((size_t)bh * DD + d) * NN + j0;
        #pragma unroll
        for (int p = 0; p < 8; p++)
            *(uint4*)&dst[p * 8] = *(const uint4*)&ts[d * VT_STR + p * 8];
    }
}

// ---------------------------------------------------------------------------
// Kernel 4: flash attention over compacted q/k/v. 3 blocks/SM enforced.
// ---------------------------------------------------------------------------
#define KS_BYTES (TK * KS_STR * 2)
#define VT_BYTES (DD * VT_STR * 2)
#define SM_KS(buf)  ((buf) * KS_BYTES)
#define SM_VT(buf)  (2 * KS_BYTES + (buf) * VT_BYTES)
#define ATT_SMEM    (2 * KS_BYTES + 2 * VT_BYTES)

__global__ __launch_bounds__(128, 3)
void attn_fp16_kernel()
{
    extern __shared__ char sm[];

    const int bid = blockIdx.x;
    const int qt  = bid & 31;
    const int bh  = bid >> 5;
    const int b   = bh >> 4;
    const int n0  = qt * BQ;

    const int cnt = g_cnt[b];
    if (n0 >= cnt) return;

    const int t    = threadIdx.x;
    const int warp = t >> 5;
    const int lane = t & 31;
    const int g    = lane >> 2;
    const int tg   = lane & 3;
    const int m0   = warp * 16;

    const __half* Qc  = g_Qc  + (size_t)bh * NN * DD;
    const __half* Kc  = g_Kc  + (size_t)bh * NN * DD;
    const __half* Vtc = g_Vtc + (size_t)bh * DD * NN;

    const unsigned smu = (unsigned)__cvta_generic_to_shared(sm);

    auto stage = [&](int kt, int buf) {
        const int k0 = kt * TK;
        const unsigned ksu = smu + SM_KS(buf);
        const unsigned vtu = smu + SM_VT(buf);
        #pragma unroll
        for (int p = 0; p < 8; p++) {
            const int c   = t + p * 128;
            const int row = c >> 4;
            const int cd  = (c & 15) * 8;
            cp16(ksu + (row * KS_STR + cd) * 2, Kc + (size_t)(k0 + row) * DD + cd);
        }
        #pragma unroll
        for (int p = 0; p < 8; p++) {
            const int c   = t + p * 128;
            const int row = c >> 3;
            const int cd  = (c & 7) * 8;
            cp16(vtu + (row * VT_STR + cd) * 2, Vtc + (size_t)row * NN + k0 + cd);
        }
        asm volatile("cp.async.commit_group;" ::: "memory");
    };

    // ---- Q fragments: direct compacted rows ----
    const int jr0 = n0 + m0 + g;
    const int jr1 = jr0 + 8;
    unsigned qa[8][4];
    {
        const __half* q0 = Qc + (size_t)jr0 * DD;
        const __half* q1 = Qc + (size_t)jr1 * DD;
        #pragma unroll
        for (int s = 0; s < 8; s++) {
            const int c = 16 * s + 2 * tg;
            qa[s][0] = *(const unsigned*)&q0[c];
            qa[s][1] = *(const unsigned*)&q1[c];
            qa[s][2] = *(const unsigned*)&q0[c + 8];
            qa[s][3] = *(const unsigned*)&q1[c + 8];
        }
    }

    const int NTc = (cnt + TK - 1) / TK;
    stage(0, 0);

    float o[16][4];
    #pragma unroll
    for (int j = 0; j < 16; j++) { o[j][0]=0.f; o[j][1]=0.f; o[j][2]=0.f; o[j][3]=0.f; }
    float l0 = 0.f, l1 = 0.f;

    for (int kt = 0; kt < NTc; kt++) {
        const int buf = kt & 1;
        const int k0  = kt * TK;
        asm volatile("cp.async.wait_group 0;" ::: "memory");
        __syncthreads();

        if (kt + 1 < NTc) stage(kt + 1, buf ^ 1);

        const __half* ks = (const __half*)(sm + SM_KS(buf));
        const __half* vt = (const __half*)(sm + SM_VT(buf));

        float sc[8][4];
        #pragma unroll
        for (int j = 0; j < 8; j++) { sc[j][0]=0.f; sc[j][1]=0.f; sc[j][2]=0.f; sc[j][3]=0.f; }

        #pragma unroll
        for (int s = 0; s < 8; s++) {
            const int dcol = 16 * s + 2 * tg;
            #pragma unroll
            for (int j = 0; j < 8; j++) {
                const unsigned b0 = *(const unsigned*)&ks[(8 * j + g) * KS_STR + dcol];
                const unsigned b1 = *(const unsigned*)&ks[(8 * j + g) * KS_STR + dcol + 8];
                mma16(sc[j], qa[s][0], qa[s][1], qa[s][2], qa[s][3], b0, b1);
            }
        }

        // ---- softmax; key validity = positional (compacted) ----
        unsigned pa[4][4];
        #pragma unroll
        for (int j = 0; j < 8; j++) {
            const int ci = 8 * j + 2 * tg;
            const bool v0 = (k0 + ci)     < cnt;
            const bool v1 = (k0 + ci + 1) < cnt;
            const float e0 = v0 ? __expf(sc[j][0]) : 0.f;
            const float e1 = v1 ? __expf(sc[j][1]) : 0.f;
            const float e2 = v0 ? __expf(sc[j][2]) : 0.f;
            const float e3 = v1 ? __expf(sc[j][3]) : 0.f;
            l0 += e0 + e1;
            l1 += e2 + e3;
            const unsigned h01 = h2pack(e0, e1);
            const unsigned h23 = h2pack(e2, e3);
            const int s2 = j >> 1;
            if ((j & 1) == 0) { pa[s2][0] = h01; pa[s2][1] = h23; }
            else              { pa[s2][2] = h01; pa[s2][3] = h23; }
        }

        #pragma unroll
        for (int s2 = 0; s2 < 4; s2++) {
            const int kcol = 16 * s2 + 2 * tg;
            #pragma unroll
            for (int j2 = 0; j2 < 16; j2++) {
                const unsigned b0 = *(const unsigned*)&vt[(8 * j2 + g) * VT_STR + kcol];
                const unsigned b1 = *(const unsigned*)&vt[(8 * j2 + g) * VT_STR + kcol + 8];
                mma16(o[j2], pa[s2][0], pa[s2][1], pa[s2][2], pa[s2][3], b0, b1);
            }
        }
        __syncthreads();
    }

    l0 += __shfl_xor_sync(0xffffffffu, l0, 1);
    l0 += __shfl_xor_sync(0xffffffffu, l0, 2);
    l1 += __shfl_xor_sync(0xffffffffu, l1, 1);
    l1 += __shfl_xor_sync(0xffffffffu, l1, 2);

    const bool  val0 = jr0 < cnt;
    const bool  val1 = jr1 < cnt;
    const float inv0 = 1.0f / l0;
    const float inv1 = 1.0f / l1;
    const int   h    = bh & 15;

    __half* ctx0 = g_Chc + ((size_t)(b * NN + jr0)) * ALLD + h * DD;
    __half* ctx1 = g_Chc + ((size_t)(b * NN + jr1)) * ALLD + h * DD;
    #pragma unroll
    for (int j2 = 0; j2 < 16; j2++) {
        const int ci = 8 * j2 + 2 * tg;
        if (val0) *(unsigned*)&ctx0[ci] = h2pack(o[j2][0] * inv0, o[j2][1] * inv0);
        if (val1) *(unsigned*)&ctx1[ci] = h2pack(o[j2][2] * inv1, o[j2][3] * inv1);
    }
}

// ---------------------------------------------------------------------------
// Kernel 5: output projection over compacted ctx rows; scatter via idx.
// ---------------------------------------------------------------------------
#define GO_AS_STR 72
#define GO_AS_BYTES (32 * GO_AS_STR * 2)
#define GO_WS_BYTES (128 * GO_AS_STR * 2)
#define GO_SM_A(buf) ((buf) * (GO_AS_BYTES + GO_WS_BYTES))
#define GO_SM_W(buf) (GO_SM_A(buf) + GO_AS_BYTES)
#define GO_SMEM (2 * (GO_AS_BYTES + GO_WS_BYTES))

__global__ __launch_bounds__(128)
void gemm_out_kernel(const float* __restrict__ bo, float* __restrict__ out)
{
    extern __shared__ char sm[];

    const int b   = blockIdx.x >> 6;
    const int r0c = (blockIdx.x & 63) * 32;
    const int cnt = g_cnt[b];
    if (r0c >= cnt) return;

    const int t    = threadIdx.x;
    const int warp = t >> 5;
    const int lane = t & 31;
    const int g    = lane >> 2;
    const int tg   = lane & 3;

    const unsigned smu = (unsigned)__cvta_generic_to_shared(sm);
    const __half* A = g_Chc + (size_t)(b * NN + r0c) * ALLD;

    auto stage = [&](int kt, int buf) {
        const int k0 = kt * 64;
        const unsigned au = smu + GO_SM_A(buf);
        const unsigned wu = smu + GO_SM_W(buf);
        #pragma unroll
        for (int p = 0; p < 2; p++) {
            const int c   = t + p * 128;
            const int row = c >> 3;
            const int cd  = (c & 7) * 8;
            cp16(au + (row * GO_AS_STR + cd) * 2, A + (size_t)row * ALLD + k0 + cd);
        }
        #pragma unroll
        for (int p = 0; p < 8; p++) {
            const int c   = t + p * 128;
            const int row = c >> 3;
            const int cd  = (c & 7) * 8;
            cp16(wu + (row * GO_AS_STR + cd) * 2, g_Wot + (size_t)row * ALLD + k0 + cd);
        }
        asm volatile("cp.async.commit_group;" ::: "memory");
    };

    stage(0, 0);

    float acc[2][4][4];
    #pragma unroll
    for (int jm = 0; jm < 2; jm++)
        #pragma unroll
        for (int jn = 0; jn < 4; jn++) {
            acc[jm][jn][0]=0.f; acc[jm][jn][1]=0.f; acc[jm][jn][2]=0.f; acc[jm][jn][3]=0.f;
        }

    for (int kt = 0; kt < 32; kt++) {
        const int buf = kt & 1;
        asm volatile("cp.async.wait_group 0;" ::: "memory");
        __syncthreads();

        if (kt + 1 < 32) stage(kt + 1, buf ^ 1);

        const __half* as = (const __half*)(sm + GO_SM_A(buf));
        const __half* ws = (const __half*)(sm + GO_SM_W(buf));

        #pragma unroll
        for (int s = 0; s < 4; s++) {
            const int kc = 16 * s + 2 * tg;
            unsigned a[2][4];
            #pragma unroll
            for (int jm = 0; jm < 2; jm++) {
                a[jm][0] = *(const unsigned*)&as[(16 * jm + g)     * GO_AS_STR + kc];
                a[jm][1] = *(const unsigned*)&as[(16 * jm + g + 8) * GO_AS_STR + kc];
                a[jm][2] = *(const unsigned*)&as[(16 * jm + g)     * GO_AS_STR + kc + 8];
                a[jm][3] = *(const unsigned*)&as[(16 * jm + g + 8) * GO_AS_STR + kc + 8];
            }
            #pragma unroll
            for (int jn = 0; jn < 4; jn++) {
                const int n = 32 * warp + 8 * jn + g;
                const unsigned b0 = *(const unsigned*)&ws[n * GO_AS_STR + kc];
                const unsigned b1 = *(const unsigned*)&ws[n * GO_AS_STR + kc + 8];
                #pragma unroll
                for (int jm = 0; jm < 2; jm++)
                    mma16(acc[jm][jn], a[jm][0], a[jm][1], a[jm][2], a[jm][3], b0, b1);
            }
        }
        __syncthreads();
    }

    const int* idx = g_idx + b * NN;
    #pragma unroll
    for (int jm = 0; jm < 2; jm++) {
        const int jrow0 = r0c + 16 * jm + g;
        const int jrow1 = jrow0 + 8;
        const bool ok0 = jrow0 < cnt;
        const bool ok1 = jrow1 < cnt;
        const int orow0 = ok0 ? (b * NN + idx[jrow0]) : 0;
        const int orow1 = ok1 ? (b * NN + idx[jrow1]) : 0;
        #pragma unroll
        for (int jn = 0; jn < 4; jn++) {
            const int col = 32 * warp + 8 * jn + 2 * tg;
            const float bb0 = bo[col], bb1 = bo[col + 1];
            float2 w0, w1;
            w0.x = acc[jm][jn][0] + bb0;  w0.y = acc[jm][jn][1] + bb1;
            w1.x = acc[jm][jn][2] + bb0;  w1.y = acc[jm][jn][3] + bb1;
            if (ok0) *(float2*)&out[(size_t)orow0 * DD + col] = w0;
            if (ok1) *(float2*)&out[(size_t)orow1 * DD + col] = w1;
        }
    }
}

// ---------------------------------------------------------------------------
// Kernel 6: fill masked output rows with bias. grid 512, 256 thr.
// ---------------------------------------------------------------------------
__global__ __launch_bounds__(256)
void fill_out_kernel(const int* __restrict__ mask,
                     const float* __restrict__ bo,
                     float* __restrict__ out)
{
    const int i = blockIdx.x * 256 + threadIdx.x;
    const int total = BN * DD;
    for (int idx = i; idx < total; idx += gridDim.x * 256) {
        const int row = idx >> 7;
        if (mask[row] == 0)
            out[idx] = __ldg(&bo[idx & 127]);
    }
}

// ---------------------------------------------------------------------------
extern "C" void kernel_launch(void* const* d_in, const int* in_sizes, int n_in,
                              void* d_out, int out_size)
{
    const float* x    = (const float*)d_in[0];
    const int*   mask = (const int*)  d_in[1];
    const float* Wq   = (const float*)d_in[2];
    const float* bq   = (const float*)d_in[3];
    const float* Wk   = (const float*)d_in[4];
    const float* bk   = (const float*)d_in[5];
    const float* Wv   = (const float*)d_in[6];
    const float* bv   = (const float*)d_in[7];
    const float* Wo   = (const float*)d_in[8];
    const float* bo   = (const float*)d_in[9];
    float* out = (float*)d_out;

    compact_kernel<<<BB, 256>>>(mask);
    convert_kernel<<<(N_CVT + 255) / 256, 256>>>(x, Wq, Wk, Wv, Wo);

    cudaFuncSetAttribute((const void*)gemm_qkv_kernel,
                         cudaFuncAttributeMaxDynamicSharedMemorySize,
                         GQ_XS_BYTES + GQ_WS_BYTES);
    gemm_qkv_kernel<<<dim3(BB * 32, 48), 128, GQ_XS_BYTES + GQ_WS_BYTES>>>(bq, bk, bv);

    cudaFuncSetAttribute((const void*)attn_fp16_kernel,
                         cudaFuncAttributeMaxDynamicSharedMemorySize, ATT_SMEM);
    attn_fp16_kernel<<<BB * HH * 32, 128, ATT_SMEM>>>();

    cudaFuncSetAttribute((const void*)gemm_out_kernel,
                         cudaFuncAttributeMaxDynamicSharedMemorySize, GO_SMEM);
    gemm_out_kernel<<<BB * 64, 128, GO_SMEM>>>(bo, out);

    fill_out_kernel<<<512, 256>>>(mask, bo, out);
}